// round 1
// baseline (speedup 1.0000x reference)
#include <cuda_runtime.h>
#include <cuda_bf16.h>
#include <math.h>

#define BB   16
#define CIN  1
#define HIN  12
#define WIN  2500
#define PP   1
#define QQ   100
#define GH   12
#define GW   25
#define LL   300          // GH*GW
#define LEN_KEEP 75
#define NTOK 76
#define DD   768
#define DH   384          // D/2
#define NHD  12
#define HD   64
#define DEPTH 12
#define MLPD 3072
#define SCALE 0.125f
#define EPS_LN 1e-5f

// ---------------- scratch (device globals; no allocation allowed) -----------
__device__ float g_hfull[BB * LL * DD];
__device__ float g_carry[BB * NTOK * DD];
__device__ float g_y[BB * NTOK * DD];
__device__ float g_qkv[BB * NTOK * 3 * DD];
__device__ float g_att[BB * NHD * NTOK * NTOK];
__device__ float g_obuf[BB * NTOK * DD];
__device__ float g_hid[BB * NTOK * MLPD];
__device__ int   g_idsk[BB * LEN_KEEP];
__device__ float g_m[BB * NTOK];
__device__ unsigned g_gmax;

// monotone float<->uint encoding for atomicMax on floats
__device__ __forceinline__ unsigned fenc(float f) {
    unsigned u = __float_as_uint(f);
    return (u & 0x80000000u) ? ~u : (u | 0x80000000u);
}
__device__ __forceinline__ float fdec(unsigned u) {
    return (u & 0x80000000u) ? __uint_as_float(u & 0x7fffffffu)
                             : __uint_as_float(~u);
}

// ---------------- patchify: conv(1x100,stride100) + pos embeds --------------
// h[b,l,d] = sum_q x[b,0,gh,gw*100+q]*conv_w[d,q] + conv_b[d]
//          + (d<384 ? pos_y_table[yids[b,l]][d]
//                   : attn_mask[b,l]*pos_embed_x[0,gw+1,d-384])
__global__ void k_patchify(const float* __restrict__ x,
                           const float* __restrict__ attn_mask,
                           const int*   __restrict__ yids,
                           const float* __restrict__ conv_w,
                           const float* __restrict__ conv_b,
                           const float* __restrict__ pex,
                           const float* __restrict__ ytab) {
    int bl = blockIdx.x;
    int b = bl / LL, l = bl % LL;
    int gh = l / GW, gw = l % GW;
    __shared__ float patch[QQ];
    const float* xrow = x + ((size_t)b * HIN + gh) * WIN + gw * QQ;
    for (int i = threadIdx.x; i < QQ; i += blockDim.x) patch[i] = xrow[i];
    __syncthreads();
    float am = attn_mask[b * LL + l];
    int yid = yids[b * LL + l];
    for (int d = threadIdx.x; d < DD; d += blockDim.x) {
        const float* w = conv_w + d * QQ;
        float acc = 0.f;
        #pragma unroll 4
        for (int q = 0; q < QQ; q++) acc += patch[q] * w[q];
        acc += conv_b[d];
        if (d < DH) acc += ytab[yid * DH + d];
        else        acc += am * pex[(gw + 1) * DH + (d - DH)];
        g_hfull[((size_t)b * LL + l) * DD + d] = acc;
    }
}

// ---------------- per-batch stable argsort + keep / mask build --------------
__global__ void k_select(const float* __restrict__ noise,
                         const float* __restrict__ attn_mask) {
    int b = blockIdx.x;
    __shared__ float ns[LL];
    __shared__ int ids[LL];
    __shared__ unsigned char keep[LL];
    for (int i = threadIdx.x; i < LL; i += blockDim.x) {
        ns[i] = noise[b * LL + i];
        keep[i] = 0;
    }
    __syncthreads();
    for (int i = threadIdx.x; i < LL; i += blockDim.x) {
        float vi = ns[i];
        int r = 0;
        for (int j = 0; j < LL; j++) {
            float vj = ns[j];
            r += (vj < vi) || (vj == vi && j < i);
        }
        ids[r] = i;
    }
    __syncthreads();
    for (int t = threadIdx.x; t < LEN_KEEP; t += blockDim.x) {
        g_idsk[b * LEN_KEEP + t] = ids[t];
        keep[ids[t]] = 1;
    }
    __syncthreads();
    for (int i = threadIdx.x; i < LL; i += blockDim.x) {
        if (keep[i]) {
            int pos = 0;
            for (int j = 0; j < i; j++) pos += keep[j];
            g_m[b * NTOK + 1 + pos] = attn_mask[b * LL + i];
        }
    }
    if (threadIdx.x == 0) g_m[b * NTOK] = 1.f;
}

// ---------------- gather kept tokens, prepend cls ---------------------------
__global__ void k_gather(const float* __restrict__ cls_token,
                         const float* __restrict__ pex) {
    int bt = blockIdx.x;
    int b = bt / NTOK, t = bt % NTOK;
    float* outp = g_carry + (size_t)bt * DD;
    if (t == 0) {
        for (int d = threadIdx.x; d < DD; d += blockDim.x)
            outp[d] = cls_token[d] + (d >= DH ? pex[d - DH] : 0.f);
    } else {
        int l = g_idsk[b * LEN_KEEP + (t - 1)];
        const float* src = g_hfull + ((size_t)b * LL + l) * DD;
        for (int d = threadIdx.x; d < DD; d += blockDim.x) outp[d] = src[d];
    }
}

// ---------------- layernorm (one block per row of 768) ----------------------
__global__ void k_ln(const float* __restrict__ in,
                     const float* __restrict__ w,
                     const float* __restrict__ bias,
                     float* __restrict__ out) {
    int r = blockIdx.x;
    const float* p = in + (size_t)r * DD;
    __shared__ float red[256];
    float s = 0.f;
    for (int d = threadIdx.x; d < DD; d += 256) s += p[d];
    red[threadIdx.x] = s; __syncthreads();
    for (int o = 128; o > 0; o >>= 1) {
        if (threadIdx.x < o) red[threadIdx.x] += red[threadIdx.x + o];
        __syncthreads();
    }
    float mu = red[0] * (1.f / DD);
    __syncthreads();
    float v = 0.f;
    for (int d = threadIdx.x; d < DD; d += 256) { float t = p[d] - mu; v += t * t; }
    red[threadIdx.x] = v; __syncthreads();
    for (int o = 128; o > 0; o >>= 1) {
        if (threadIdx.x < o) red[threadIdx.x] += red[threadIdx.x + o];
        __syncthreads();
    }
    float rstd = rsqrtf(red[0] * (1.f / DD) + EPS_LN);
    for (int d = threadIdx.x; d < DD; d += 256)
        out[(size_t)r * DD + d] = (p[d] - mu) * rstd * w[d] + bias[d];
}

// ---------------- generic SGEMM: C = A[M,K] @ W[N,K]^T + bias (+res/+gelu) --
// MODE 0: bias; MODE 1: bias+gelu(exact); MODE 2: bias+residual
template <int MODE>
__global__ void k_gemm(const float* __restrict__ A,
                       const float* __restrict__ W,
                       const float* __restrict__ bias,
                       const float* __restrict__ res,
                       float* __restrict__ C, int M, int N, int K) {
    __shared__ float As[16][64];
    __shared__ float Ws[16][64];
    int m0 = blockIdx.y * 64, n0 = blockIdx.x * 64;
    int tid = threadIdx.x;
    int tx = tid & 15, ty = tid >> 4;
    float acc[4][4] = {};
    for (int k0 = 0; k0 < K; k0 += 16) {
        #pragma unroll
        for (int i = 0; i < 4; i++) {
            int idx = tid + i * 256;
            int mm = idx >> 4, kk = idx & 15;
            As[kk][mm] = A[(size_t)(m0 + mm) * K + k0 + kk];
            Ws[kk][mm] = W[(size_t)(n0 + mm) * K + k0 + kk];
        }
        __syncthreads();
        #pragma unroll
        for (int kk = 0; kk < 16; kk++) {
            float4 a4 = *(const float4*)&As[kk][ty * 4];
            float4 b4 = *(const float4*)&Ws[kk][tx * 4];
            float av[4] = {a4.x, a4.y, a4.z, a4.w};
            float bv[4] = {b4.x, b4.y, b4.z, b4.w};
            #pragma unroll
            for (int i = 0; i < 4; i++)
                #pragma unroll
                for (int j = 0; j < 4; j++) acc[i][j] += av[i] * bv[j];
        }
        __syncthreads();
    }
    #pragma unroll
    for (int i = 0; i < 4; i++) {
        int m = m0 + ty * 4 + i;
        #pragma unroll
        for (int j = 0; j < 4; j++) {
            int n = n0 + tx * 4 + j;
            float v = acc[i][j] + bias[n];
            if (MODE == 1) v = 0.5f * v * (1.f + erff(v * 0.70710678118654752f));
            if (MODE == 2) v += res[(size_t)m * N + n];
            C[(size_t)m * N + n] = v;
        }
    }
}

// ---------------- attention: scores + global max ----------------------------
__global__ void k_reset_gmax() { g_gmax = 0u; }

__global__ void k_scores() {
    int idx = blockIdx.x;                 // (b*NH + h)*NTOK + n
    int n = idx % NTOK;
    int bh = idx / NTOK;
    int h = bh % NHD, b = bh / NHD;
    __shared__ float qsh[HD];
    __shared__ float red[128];
    const float* qp = g_qkv + (size_t)(b * NTOK + n) * (3 * DD) + h * HD;
    if (threadIdx.x < HD) qsh[threadIdx.x] = qp[threadIdx.x];
    __syncthreads();
    float mn = g_m[b * NTOK + n];
    float lmax = -3.4e38f;
    int m = threadIdx.x;
    if (m < NTOK) {
        const float* kp = g_qkv + (size_t)(b * NTOK + m) * (3 * DD) + DD + h * HD;
        float dot = 0.f;
        #pragma unroll
        for (int d = 0; d < HD; d++) dot += qsh[d] * kp[d];
        float logit = dot * SCALE;
        float mm = mn * g_m[b * NTOK + m];
        if (mm == 0.f) logit = -INFINITY; else lmax = logit;
        g_att[(size_t)idx * NTOK + m] = logit;
    }
    red[threadIdx.x] = lmax; __syncthreads();
    for (int o = 64; o > 0; o >>= 1) {
        if (threadIdx.x < o) red[threadIdx.x] = fmaxf(red[threadIdx.x], red[threadIdx.x + o]);
        __syncthreads();
    }
    if (threadIdx.x == 0 && red[0] > -3.3e38f) atomicMax(&g_gmax, fenc(red[0]));
}

// ---------------- softmax (global-max variant) + AV -------------------------
__global__ void k_softmax_av() {
    int idx = blockIdx.x;
    int n = idx % NTOK;
    int bh = idx / NTOK;
    int h = bh % NHD, b = bh / NHD;
    __shared__ float p[NTOK];
    __shared__ float red[128];
    float g = fdec(g_gmax);
    float e = 0.f;
    if (threadIdx.x < NTOK) {
        e = expf(g_att[(size_t)idx * NTOK + threadIdx.x] - g);
        p[threadIdx.x] = e;
    }
    red[threadIdx.x] = e; __syncthreads();
    for (int o = 64; o > 0; o >>= 1) {
        if (threadIdx.x < o) red[threadIdx.x] += red[threadIdx.x + o];
        __syncthreads();
    }
    float inv = 1.f / (red[0] + 1e-9f);
    if (threadIdx.x < HD) {
        const float* vp = g_qkv + (size_t)(b * NTOK) * (3 * DD) + 2 * DD + h * HD + threadIdx.x;
        float acc = 0.f;
        for (int m2 = 0; m2 < NTOK; m2++) acc += p[m2] * vp[(size_t)m2 * 3 * DD];
        g_obuf[(size_t)(b * NTOK + n) * DD + h * HD + threadIdx.x] = acc * inv;
    }
}

// ---------------- launch ----------------------------------------------------
extern "C" void kernel_launch(void* const* d_in, const int* in_sizes, int n_in,
                              void* d_out, int out_size) {
    const float* x         = (const float*)d_in[0];
    const float* attn_mask = (const float*)d_in[1];
    const int*   yids      = (const int*)  d_in[2];
    const float* noise     = (const float*)d_in[3];
    const float* conv_w    = (const float*)d_in[4];
    const float* conv_b    = (const float*)d_in[5];
    const float* pex       = (const float*)d_in[6];
    const float* ytab      = (const float*)d_in[7];
    const float* cls       = (const float*)d_in[8];
    const float* qkv_w     = (const float*)d_in[9];
    const float* qkv_b     = (const float*)d_in[10];
    const float* proj_w    = (const float*)d_in[11];
    const float* proj_b    = (const float*)d_in[12];
    const float* ln1_w     = (const float*)d_in[13];
    const float* ln1_b     = (const float*)d_in[14];
    const float* ln2_w     = (const float*)d_in[15];
    const float* ln2_b     = (const float*)d_in[16];
    const float* fc1_w     = (const float*)d_in[17];
    const float* fc1_b     = (const float*)d_in[18];
    const float* fc2_w     = (const float*)d_in[19];
    const float* fc2_b     = (const float*)d_in[20];
    const float* norm_w    = (const float*)d_in[21];
    const float* norm_b    = (const float*)d_in[22];
    float* out = (float*)d_out;

    float *carry, *ybuf, *qkv, *obuf, *hid;
    cudaGetSymbolAddress((void**)&carry, g_carry);
    cudaGetSymbolAddress((void**)&ybuf,  g_y);
    cudaGetSymbolAddress((void**)&qkv,   g_qkv);
    cudaGetSymbolAddress((void**)&obuf,  g_obuf);
    cudaGetSymbolAddress((void**)&hid,   g_hid);

    const int M = BB * NTOK;   // 1216

    // prologue
    k_patchify<<<BB * LL, 256>>>(x, attn_mask, yids, conv_w, conv_b, pex, ytab);
    k_select<<<BB, 256>>>(noise, attn_mask);
    k_gather<<<BB * NTOK, 256>>>(cls, pex);

    for (int l = 0; l < DEPTH; l++) {
        const float* qw  = qkv_w  + (size_t)l * 3 * DD * DD;
        const float* qb  = qkv_b  + (size_t)l * 3 * DD;
        const float* pw  = proj_w + (size_t)l * DD * DD;
        const float* pb  = proj_b + (size_t)l * DD;
        const float* l1w = ln1_w + l * DD; const float* l1b = ln1_b + l * DD;
        const float* l2w = ln2_w + l * DD; const float* l2b = ln2_b + l * DD;
        const float* f1w = fc1_w + (size_t)l * MLPD * DD;
        const float* f1b = fc1_b + (size_t)l * MLPD;
        const float* f2w = fc2_w + (size_t)l * DD * MLPD;
        const float* f2b = fc2_b + (size_t)l * DD;

        k_ln<<<M, 256>>>(carry, l1w, l1b, ybuf);
        k_gemm<0><<<dim3(3 * DD / 64, M / 64), 256>>>(ybuf, qw, qb, nullptr, qkv, M, 3 * DD, DD);
        k_reset_gmax<<<1, 1>>>();
        k_scores<<<BB * NHD * NTOK, 128>>>();
        k_softmax_av<<<BB * NHD * NTOK, 128>>>();
        k_gemm<2><<<dim3(DD / 64, M / 64), 256>>>(obuf, pw, pb, carry, carry, M, DD, DD);
        k_ln<<<M, 256>>>(carry, l2w, l2b, ybuf);
        k_gemm<1><<<dim3(MLPD / 64, M / 64), 256>>>(ybuf, f1w, f1b, nullptr, hid, M, MLPD, DD);
        k_gemm<2><<<dim3(DD / 64, M / 64), 256>>>(hid, f2w, f2b, carry, carry, M, DD, MLPD);
    }

    k_ln<<<M, 256>>>(carry, norm_w, norm_b, out);
}

// round 5
// speedup vs baseline: 2.1393x; 2.1393x over previous
#include <cuda_runtime.h>
#include <cuda_bf16.h>
#include <math.h>
#include <cstdint>

#define BB   16
#define HIN  12
#define WIN  2500
#define QQ   100
#define GW   25
#define LL   300
#define LEN_KEEP 75
#define NTOK 76
#define DD   768
#define DH   384
#define NHD  12
#define HD   64
#define DEPTH 12
#define MLPD 3072
#define SCALE 0.125f
#define EPS_LN 1e-5f
#define MROWS (BB * NTOK)     // 1216
#define M_PAD 1280            // 10 tiles of 128

// ---------------- scratch (device globals; no allocation allowed) -----------
__device__ float g_hfull[BB * LL * DD];
__device__ float g_carry[M_PAD * DD];
__device__ float g_y[M_PAD * DD];
__device__ float g_qkv[M_PAD * 3 * DD];
__device__ float g_att[BB * NHD * NTOK * NTOK];
__device__ float g_obuf[M_PAD * DD];
__device__ float g_hid[M_PAD * MLPD];
__device__ int   g_idsk[BB * LEN_KEEP];
__device__ float g_m[BB * NTOK];
__device__ unsigned g_gmax;

// monotone float<->uint encoding for atomicMax on floats
__device__ __forceinline__ unsigned fenc(float f) {
    unsigned u = __float_as_uint(f);
    return (u & 0x80000000u) ? ~u : (u | 0x80000000u);
}
__device__ __forceinline__ float fdec(unsigned u) {
    return (u & 0x80000000u) ? __uint_as_float(u & 0x7fffffffu) : __uint_as_float(~u);
}

// ---------------- bf16x2 split helper ----------------------------------------
// pack (x0,x1) into bf16x2 words: bw = big parts, sw = residual parts
__device__ __forceinline__ void split2(float x0, float x1,
                                       uint32_t& bw, uint32_t& sw) {
    __nv_bfloat16 b0 = __float2bfloat16(x0);
    __nv_bfloat16 b1 = __float2bfloat16(x1);
    float r0 = x0 - __bfloat162float(b0);
    float r1 = x1 - __bfloat162float(b1);
    __nv_bfloat16 s0 = __float2bfloat16(r0);
    __nv_bfloat16 s1 = __float2bfloat16(r1);
    bw = (uint32_t)__bfloat16_as_ushort(b0) | ((uint32_t)__bfloat16_as_ushort(b1) << 16);
    sw = (uint32_t)__bfloat16_as_ushort(s0) | ((uint32_t)__bfloat16_as_ushort(s1) << 16);
}

__device__ __forceinline__ void mma_bf16(float* d, uint32_t a0, uint32_t a1,
                                         uint32_t a2, uint32_t a3,
                                         uint32_t b0, uint32_t b1) {
    asm volatile(
        "mma.sync.aligned.m16n8k16.row.col.f32.bf16.bf16.f32 "
        "{%0,%1,%2,%3}, {%4,%5,%6,%7}, {%8,%9}, {%0,%1,%2,%3};"
        : "+f"(d[0]), "+f"(d[1]), "+f"(d[2]), "+f"(d[3])
        : "r"(a0), "r"(a1), "r"(a2), "r"(a3), "r"(b0), "r"(b1));
}

// ---------------- bf16x3 GEMM: C = A[M,K] @ W[N,K]^T + bias (+ops) ----------
// BM=128, BK=32, 256 threads (8 warps: 4 M x 2 N). Warp tile 32 x BN/2.
// smem per stage: Abig[128][20w] Asmall[128][20w] Wbig[BN][20w] Wsmall[BN][20w]
// (uint32 words, each = 2 packed bf16 for k-pair). Row uses 16 words, stride 20.
// MODE 0: bias; 1: bias+gelu(exact); 2: bias+residual
#define RSTR 20
template <int BN, int MODE>
__global__ void __launch_bounds__(256)
k_gemm_mma(const float* __restrict__ A, const float* __restrict__ W,
           const float* __restrict__ bias, const float* __restrict__ res,
           float* __restrict__ C, int Ncols, int K) {
    extern __shared__ uint32_t sh[];
    const int STAGE = (128 + BN) * 2 * RSTR;   // words per stage
    const int AW = 128 * RSTR;                 // words of one A tile
    const int WW = BN * RSTR;

    const int tid = threadIdx.x;
    const int wid = tid >> 5, lane = tid & 31;
    const int g = lane >> 2, t = lane & 3;
    const int warp_m = wid & 3, warp_n = wid >> 2;
    const int wm0 = warp_m * 32;
    const int wn0 = warp_n * (BN / 2);
    const int m0 = blockIdx.y * 128, n0 = blockIdx.x * BN;
    const int NI = BN / 16;                    // 8 or 4
    const int AF4 = 128 * 8;                   // float4 loads for A chunk
    const int NF4 = AF4 + BN * 8;
    const int NIT = NF4 / 256;                 // 8 or 6
    const int nC = K >> 5;

    float acc[2][BN / 16][4];
    #pragma unroll
    for (int mi = 0; mi < 2; mi++)
        #pragma unroll
        for (int ni = 0; ni < NI; ni++)
            #pragma unroll
            for (int j = 0; j < 4; j++) acc[mi][ni][j] = 0.f;

    float4 buf[NIT];

    auto ldg_chunk = [&](int c) {
        int k0 = c << 5;
        #pragma unroll
        for (int it = 0; it < NIT; it++) {
            int i = tid + it * 256;
            const float* src;
            if (i < AF4) {
                int row = i >> 3, c4 = i & 7;
                src = A + (size_t)(m0 + row) * K + k0 + c4 * 4;
            } else {
                int j = i - AF4;
                int row = j >> 3, c4 = j & 7;
                src = W + (size_t)(n0 + row) * K + k0 + c4 * 4;
            }
            buf[it] = *(const float4*)src;
        }
    };

    auto sts_chunk = [&](int s) {
        uint32_t* base = sh + s * STAGE;
        #pragma unroll
        for (int it = 0; it < NIT; it++) {
            int i = tid + it * 256;
            float4 v = buf[it];
            uint32_t bw0, sw0, bw1, sw1;
            split2(v.x, v.y, bw0, sw0);
            split2(v.z, v.w, bw1, sw1);
            uint32_t *bp, *sp;
            int row, c4;
            if (i < AF4) {
                row = i >> 3; c4 = i & 7;
                bp = base;            sp = base + AW;
            } else {
                int j = i - AF4;
                row = j >> 3; c4 = j & 7;
                bp = base + 2 * AW;   sp = base + 2 * AW + WW;
            }
            *(uint2*)&bp[row * RSTR + c4 * 2] = make_uint2(bw0, bw1);
            *(uint2*)&sp[row * RSTR + c4 * 2] = make_uint2(sw0, sw1);
        }
    };

    auto compute = [&](int s) {
        const uint32_t* Ab = sh + s * STAGE;
        const uint32_t* As = Ab + AW;
        const uint32_t* Wb = As + AW;
        const uint32_t* Ws = Wb + WW;
        #pragma unroll
        for (int ks = 0; ks < 2; ks++) {
            int w0 = ks * 8 + t;
            uint32_t ab[2][4], asm_[2][4];
            #pragma unroll
            for (int mi = 0; mi < 2; mi++) {
                int r = wm0 + mi * 16 + g;
                ab[mi][0]  = Ab[r * RSTR + w0];
                ab[mi][1]  = Ab[(r + 8) * RSTR + w0];
                ab[mi][2]  = Ab[r * RSTR + w0 + 4];
                ab[mi][3]  = Ab[(r + 8) * RSTR + w0 + 4];
                asm_[mi][0] = As[r * RSTR + w0];
                asm_[mi][1] = As[(r + 8) * RSTR + w0];
                asm_[mi][2] = As[r * RSTR + w0 + 4];
                asm_[mi][3] = As[(r + 8) * RSTR + w0 + 4];
            }
            #pragma unroll
            for (int ni = 0; ni < NI; ni++) {
                int cb = wn0 + ni * 8 + g;
                uint32_t b0b = Wb[cb * RSTR + w0];
                uint32_t b1b = Wb[cb * RSTR + w0 + 4];
                uint32_t b0s = Ws[cb * RSTR + w0];
                uint32_t b1s = Ws[cb * RSTR + w0 + 4];
                #pragma unroll
                for (int mi = 0; mi < 2; mi++) {
                    mma_bf16(acc[mi][ni], ab[mi][0], ab[mi][1], ab[mi][2], ab[mi][3], b0b, b1b);
                    mma_bf16(acc[mi][ni], asm_[mi][0], asm_[mi][1], asm_[mi][2], asm_[mi][3], b0b, b1b);
                    mma_bf16(acc[mi][ni], ab[mi][0], ab[mi][1], ab[mi][2], ab[mi][3], b0s, b1s);
                }
            }
        }
    };

    ldg_chunk(0);
    sts_chunk(0);
    __syncthreads();

    for (int c = 0; c < nC; c++) {
        int s = c & 1;
        if (c + 1 < nC) ldg_chunk(c + 1);
        compute(s);
        if (c + 1 < nC) sts_chunk(s ^ 1);
        __syncthreads();
    }

    // epilogue: c0,c1 -> row g, cols 2t,2t+1 ; c2,c3 -> row g+8
    #pragma unroll
    for (int mi = 0; mi < 2; mi++) {
        int r0 = m0 + wm0 + mi * 16 + g;
        int r1 = r0 + 8;
        #pragma unroll
        for (int ni = 0; ni < NI; ni++) {
            int n = n0 + wn0 + ni * 8 + 2 * t;
            float b0 = bias[n], b1 = bias[n + 1];
            float v0 = acc[mi][ni][0] + b0;
            float v1 = acc[mi][ni][1] + b1;
            float v2 = acc[mi][ni][2] + b0;
            float v3 = acc[mi][ni][3] + b1;
            if (MODE == 1) {
                v0 = 0.5f * v0 * (1.f + erff(v0 * 0.70710678118654752f));
                v1 = 0.5f * v1 * (1.f + erff(v1 * 0.70710678118654752f));
                v2 = 0.5f * v2 * (1.f + erff(v2 * 0.70710678118654752f));
                v3 = 0.5f * v3 * (1.f + erff(v3 * 0.70710678118654752f));
            }
            if (MODE == 2) {
                v0 += res[(size_t)r0 * Ncols + n];
                v1 += res[(size_t)r0 * Ncols + n + 1];
                v2 += res[(size_t)r1 * Ncols + n];
                v3 += res[(size_t)r1 * Ncols + n + 1];
            }
            *(float2*)&C[(size_t)r0 * Ncols + n] = make_float2(v0, v1);
            *(float2*)&C[(size_t)r1 * Ncols + n] = make_float2(v2, v3);
        }
    }
}

// ---------------- patchify ---------------------------------------------------
__global__ void k_patchify(const float* __restrict__ x,
                           const float* __restrict__ attn_mask,
                           const int*   __restrict__ yids,
                           const float* __restrict__ conv_w,
                           const float* __restrict__ conv_b,
                           const float* __restrict__ pex,
                           const float* __restrict__ ytab) {
    int bl = blockIdx.x;
    int b = bl / LL, l = bl % LL;
    int gh = l / GW, gw = l % GW;
    __shared__ float patch[QQ];
    const float* xrow = x + ((size_t)b * HIN + gh) * WIN + gw * QQ;
    for (int i = threadIdx.x; i < QQ; i += blockDim.x) patch[i] = xrow[i];
    __syncthreads();
    float am = attn_mask[b * LL + l];
    int yid = yids[b * LL + l];
    for (int d = threadIdx.x; d < DD; d += blockDim.x) {
        const float* w = conv_w + d * QQ;
        float acc = 0.f;
        #pragma unroll 4
        for (int q = 0; q < QQ; q++) acc += patch[q] * w[q];
        acc += conv_b[d];
        if (d < DH) acc += ytab[yid * DH + d];
        else        acc += am * pex[(gw + 1) * DH + (d - DH)];
        g_hfull[((size_t)b * LL + l) * DD + d] = acc;
    }
}

// ---------------- per-batch stable argsort + keep / mask build ---------------
__global__ void k_select(const float* __restrict__ noise,
                         const float* __restrict__ attn_mask) {
    int b = blockIdx.x;
    __shared__ float ns[LL];
    __shared__ int ids[LL];
    __shared__ unsigned char keep[LL];
    for (int i = threadIdx.x; i < LL; i += blockDim.x) { ns[i] = noise[b * LL + i]; keep[i] = 0; }
    __syncthreads();
    for (int i = threadIdx.x; i < LL; i += blockDim.x) {
        float vi = ns[i];
        int r = 0;
        for (int j = 0; j < LL; j++) {
            float vj = ns[j];
            r += (vj < vi) || (vj == vi && j < i);
        }
        ids[r] = i;
    }
    __syncthreads();
    for (int t = threadIdx.x; t < LEN_KEEP; t += blockDim.x) {
        g_idsk[b * LEN_KEEP + t] = ids[t];
        keep[ids[t]] = 1;
    }
    __syncthreads();
    for (int i = threadIdx.x; i < LL; i += blockDim.x) {
        if (keep[i]) {
            int pos = 0;
            for (int j = 0; j < i; j++) pos += keep[j];
            g_m[b * NTOK + 1 + pos] = attn_mask[b * LL + i];
        }
    }
    if (threadIdx.x == 0) g_m[b * NTOK] = 1.f;
}

// ---------------- gather kept tokens, prepend cls ----------------------------
__global__ void k_gather(const float* __restrict__ cls_token,
                         const float* __restrict__ pex) {
    int bt = blockIdx.x;
    int b = bt / NTOK, t = bt % NTOK;
    float* outp = g_carry + (size_t)bt * DD;
    if (t == 0) {
        for (int d = threadIdx.x; d < DD; d += blockDim.x)
            outp[d] = cls_token[d] + (d >= DH ? pex[d - DH] : 0.f);
    } else {
        int l = g_idsk[b * LEN_KEEP + (t - 1)];
        const float* src = g_hfull + ((size_t)b * LL + l) * DD;
        for (int d = threadIdx.x; d < DD; d += blockDim.x) outp[d] = src[d];
    }
}

// ---------------- layernorm --------------------------------------------------
__global__ void k_ln(const float* __restrict__ in,
                     const float* __restrict__ w,
                     const float* __restrict__ bias,
                     float* __restrict__ out) {
    int r = blockIdx.x;
    const float* p = in + (size_t)r * DD;
    __shared__ float red[256];
    float s = 0.f;
    for (int d = threadIdx.x; d < DD; d += 256) s += p[d];
    red[threadIdx.x] = s; __syncthreads();
    for (int o = 128; o > 0; o >>= 1) {
        if (threadIdx.x < o) red[threadIdx.x] += red[threadIdx.x + o];
        __syncthreads();
    }
    float mu = red[0] * (1.f / DD);
    __syncthreads();
    float v = 0.f;
    for (int d = threadIdx.x; d < DD; d += 256) { float t = p[d] - mu; v += t * t; }
    red[threadIdx.x] = v; __syncthreads();
    for (int o = 128; o > 0; o >>= 1) {
        if (threadIdx.x < o) red[threadIdx.x] += red[threadIdx.x + o];
        __syncthreads();
    }
    float rstd = rsqrtf(red[0] * (1.f / DD) + EPS_LN);
    for (int d = threadIdx.x; d < DD; d += 256)
        out[(size_t)r * DD + d] = (p[d] - mu) * rstd * w[d] + bias[d];
}

// ---------------- attention: scores + global max -----------------------------
__global__ void k_reset_gmax() { g_gmax = 0u; }

__global__ void k_scores() {
    int idx = blockIdx.x;
    int n = idx % NTOK;
    int bh = idx / NTOK;
    int h = bh % NHD, b = bh / NHD;
    __shared__ float qsh[HD];
    __shared__ float red[128];
    const float* qp = g_qkv + (size_t)(b * NTOK + n) * (3 * DD) + h * HD;
    if (threadIdx.x < HD) qsh[threadIdx.x] = qp[threadIdx.x];
    __syncthreads();
    float mn = g_m[b * NTOK + n];
    float lmax = -3.4e38f;
    int m = threadIdx.x;
    if (m < NTOK) {
        const float* kp = g_qkv + (size_t)(b * NTOK + m) * (3 * DD) + DD + h * HD;
        float dot = 0.f;
        #pragma unroll
        for (int d = 0; d < HD; d++) dot += qsh[d] * kp[d];
        float logit = dot * SCALE;
        float mm = mn * g_m[b * NTOK + m];
        if (mm == 0.f) logit = -INFINITY; else lmax = logit;
        g_att[(size_t)idx * NTOK + m] = logit;
    }
    red[threadIdx.x] = lmax; __syncthreads();
    for (int o = 64; o > 0; o >>= 1) {
        if (threadIdx.x < o) red[threadIdx.x] = fmaxf(red[threadIdx.x], red[threadIdx.x + o]);
        __syncthreads();
    }
    if (threadIdx.x == 0 && red[0] > -3.3e38f) atomicMax(&g_gmax, fenc(red[0]));
}

// ---------------- softmax (global-max variant) + AV --------------------------
__global__ void k_softmax_av() {
    int idx = blockIdx.x;
    int n = idx % NTOK;
    int bh = idx / NTOK;
    int h = bh % NHD, b = bh / NHD;
    __shared__ float p[NTOK];
    __shared__ float red[128];
    float g = fdec(g_gmax);
    float e = 0.f;
    if (threadIdx.x < NTOK) {
        e = expf(g_att[(size_t)idx * NTOK + threadIdx.x] - g);
        p[threadIdx.x] = e;
    }
    red[threadIdx.x] = e; __syncthreads();
    for (int o = 64; o > 0; o >>= 1) {
        if (threadIdx.x < o) red[threadIdx.x] += red[threadIdx.x + o];
        __syncthreads();
    }
    float inv = 1.f / (red[0] + 1e-9f);
    if (threadIdx.x < HD) {
        const float* vp = g_qkv + (size_t)(b * NTOK) * (3 * DD) + 2 * DD + h * HD + threadIdx.x;
        float acc = 0.f;
        for (int m2 = 0; m2 < NTOK; m2++) acc += p[m2] * vp[(size_t)m2 * 3 * DD];
        g_obuf[(size_t)(b * NTOK + n) * DD + h * HD + threadIdx.x] = acc * inv;
    }
}

// ---------------- launch -----------------------------------------------------
extern "C" void kernel_launch(void* const* d_in, const int* in_sizes, int n_in,
                              void* d_out, int out_size) {
    const float* x         = (const float*)d_in[0];
    const float* attn_mask = (const float*)d_in[1];
    const int*   yids      = (const int*)  d_in[2];
    const float* noise     = (const float*)d_in[3];
    const float* conv_w    = (const float*)d_in[4];
    const float* conv_b    = (const float*)d_in[5];
    const float* pex       = (const float*)d_in[6];
    const float* ytab      = (const float*)d_in[7];
    const float* cls       = (const float*)d_in[8];
    const float* qkv_w     = (const float*)d_in[9];
    const float* qkv_b     = (const float*)d_in[10];
    const float* proj_w    = (const float*)d_in[11];
    const float* proj_b    = (const float*)d_in[12];
    const float* ln1_w     = (const float*)d_in[13];
    const float* ln1_b     = (const float*)d_in[14];
    const float* ln2_w     = (const float*)d_in[15];
    const float* ln2_b     = (const float*)d_in[16];
    const float* fc1_w     = (const float*)d_in[17];
    const float* fc1_b     = (const float*)d_in[18];
    const float* fc2_w     = (const float*)d_in[19];
    const float* fc2_b     = (const float*)d_in[20];
    const float* norm_w    = (const float*)d_in[21];
    const float* norm_b    = (const float*)d_in[22];
    float* out = (float*)d_out;

    float *carry, *ybuf, *qkv, *obuf, *hid;
    cudaGetSymbolAddress((void**)&carry, g_carry);
    cudaGetSymbolAddress((void**)&ybuf,  g_y);
    cudaGetSymbolAddress((void**)&qkv,   g_qkv);
    cudaGetSymbolAddress((void**)&obuf,  g_obuf);
    cudaGetSymbolAddress((void**)&hid,   g_hid);

    const int SM128 = 2 * (128 + 128) * 2 * RSTR * 4;  // 81920 bytes
    const int SM64  = 2 * (128 + 64)  * 2 * RSTR * 4;  // 61440 bytes
    cudaFuncSetAttribute(k_gemm_mma<128, 0>, cudaFuncAttributeMaxDynamicSharedMemorySize, SM128);
    cudaFuncSetAttribute(k_gemm_mma<128, 1>, cudaFuncAttributeMaxDynamicSharedMemorySize, SM128);
    cudaFuncSetAttribute(k_gemm_mma<64, 2>,  cudaFuncAttributeMaxDynamicSharedMemorySize, SM64);

    const int MT = M_PAD / 128;  // 10

    // prologue
    k_patchify<<<BB * LL, 256>>>(x, attn_mask, yids, conv_w, conv_b, pex, ytab);
    k_select<<<BB, 256>>>(noise, attn_mask);
    k_gather<<<BB * NTOK, 256>>>(cls, pex);

    for (int l = 0; l < DEPTH; l++) {
        const float* qw  = qkv_w  + (size_t)l * 3 * DD * DD;
        const float* qb  = qkv_b  + (size_t)l * 3 * DD;
        const float* pw  = proj_w + (size_t)l * DD * DD;
        const float* pb  = proj_b + (size_t)l * DD;
        const float* l1w = ln1_w + l * DD; const float* l1b = ln1_b + l * DD;
        const float* l2w = ln2_w + l * DD; const float* l2b = ln2_b + l * DD;
        const float* f1w = fc1_w + (size_t)l * MLPD * DD;
        const float* f1b = fc1_b + (size_t)l * MLPD;
        const float* f2w = fc2_w + (size_t)l * DD * MLPD;
        const float* f2b = fc2_b + (size_t)l * DD;

        k_ln<<<MROWS, 256>>>(carry, l1w, l1b, ybuf);
        k_gemm_mma<128, 0><<<dim3(3 * DD / 128, MT), 256, SM128>>>(ybuf, qw, qb, nullptr, qkv, 3 * DD, DD);
        k_reset_gmax<<<1, 1>>>();
        k_scores<<<BB * NHD * NTOK, 128>>>();
        k_softmax_av<<<BB * NHD * NTOK, 128>>>();
        k_gemm_mma<64, 2><<<dim3(DD / 64, MT), 256, SM64>>>(obuf, pw, pb, carry, carry, DD, DD);
        k_ln<<<MROWS, 256>>>(carry, l2w, l2b, ybuf);
        k_gemm_mma<128, 1><<<dim3(MLPD / 128, MT), 256, SM128>>>(ybuf, f1w, f1b, nullptr, hid, MLPD, DD);
        k_gemm_mma<64, 2><<<dim3(DD / 64, MT), 256, SM64>>>(hid, f2w, f2b, carry, carry, DD, MLPD);
    }

    k_ln<<<MROWS, 256>>>(carry, norm_w, norm_b, out);
}

// round 6
// speedup vs baseline: 2.2601x; 1.0565x over previous
#include <cuda_runtime.h>
#include <cuda_bf16.h>
#include <math.h>
#include <cstdint>

#define BB   16
#define HIN  12
#define WIN  2500
#define QQ   100
#define GW   25
#define LL   300
#define LEN_KEEP 75
#define NTOK 76
#define DD   768
#define DH   384
#define NHD  12
#define HD   64
#define DEPTH 12
#define MLPD 3072
#define SCALE 0.125f
#define EPS_LN 1e-5f
#define MROWS (BB * NTOK)     // 1216
#define M_PAD 1280            // 10 tiles of 128

#define QWN  (DEPTH * 3 * DD * DD)
#define PWN  (DEPTH * DD * DD)
#define F1N  (DEPTH * MLPD * DD)
#define F2N  (DEPTH * DD * MLPD)

// ---------------- scratch (device globals; no allocation allowed) -----------
__device__ float g_hfull[BB * LL * DD];
__device__ float g_carry[M_PAD * DD];
__device__ float g_qkv[M_PAD * 3 * DD];
__device__ float g_att[BB * NHD * NTOK * NTOK];
__device__ int   g_idsk[BB * LEN_KEEP];
__device__ float g_m[BB * NTOK];
__device__ unsigned g_gmax;

// split activations (big/small bf16)
__device__ __nv_bfloat16 g_actb[M_PAD * DD],   g_acts[M_PAD * DD];
__device__ __nv_bfloat16 g_hidb[M_PAD * MLPD], g_hids[M_PAD * MLPD];
// split weights
__device__ __nv_bfloat16 g_wqb[QWN], g_wqs[QWN];
__device__ __nv_bfloat16 g_wpb[PWN], g_wps[PWN];
__device__ __nv_bfloat16 g_w1b[F1N], g_w1s[F1N];
__device__ __nv_bfloat16 g_w2b[F2N], g_w2s[F2N];

// monotone float<->uint encoding for atomicMax on floats
__device__ __forceinline__ unsigned fenc(float f) {
    unsigned u = __float_as_uint(f);
    return (u & 0x80000000u) ? ~u : (u | 0x80000000u);
}
__device__ __forceinline__ float fdec(unsigned u) {
    return (u & 0x80000000u) ? __uint_as_float(u & 0x7fffffffu) : __uint_as_float(~u);
}

// ---------------- asm helpers -------------------------------------------------
#define CP_ASYNC16(dst, src) \
    asm volatile("cp.async.cg.shared.global [%0], [%1], 16;" :: "r"(dst), "l"(src))
#define CP_COMMIT() asm volatile("cp.async.commit_group;" ::: "memory")
#define LDSM4(r0, r1, r2, r3, addr)                                          \
    asm volatile("ldmatrix.sync.aligned.m8n8.x4.shared.b16 {%0,%1,%2,%3}, [%4];" \
        : "=r"(r0), "=r"(r1), "=r"(r2), "=r"(r3) : "r"(addr))

__device__ __forceinline__ void mma_bf16(float* d, const uint32_t* a,
                                         uint32_t b0, uint32_t b1) {
    asm volatile(
        "mma.sync.aligned.m16n8k16.row.col.f32.bf16.bf16.f32 "
        "{%0,%1,%2,%3}, {%4,%5,%6,%7}, {%8,%9}, {%0,%1,%2,%3};"
        : "+f"(d[0]), "+f"(d[1]), "+f"(d[2]), "+f"(d[3])
        : "r"(a[0]), "r"(a[1]), "r"(a[2]), "r"(a[3]), "r"(b0), "r"(b1));
}

__device__ __forceinline__ uint32_t pack_big(float v0, float v1, float& r0, float& r1) {
    __nv_bfloat16 b0 = __float2bfloat16(v0);
    __nv_bfloat16 b1 = __float2bfloat16(v1);
    r0 = v0 - __bfloat162float(b0);
    r1 = v1 - __bfloat162float(b1);
    return (uint32_t)__bfloat16_as_ushort(b0) | ((uint32_t)__bfloat16_as_ushort(b1) << 16);
}
__device__ __forceinline__ uint32_t pack_bf2(float v0, float v1) {
    __nv_bfloat16 b0 = __float2bfloat16(v0);
    __nv_bfloat16 b1 = __float2bfloat16(v1);
    return (uint32_t)__bfloat16_as_ushort(b0) | ((uint32_t)__bfloat16_as_ushort(b1) << 16);
}

// ---------------- weight split kernel -----------------------------------------
__global__ void k_split(const float4* __restrict__ src,
                        __nv_bfloat16* __restrict__ dstb,
                        __nv_bfloat16* __restrict__ dsts, int n4) {
    int i = blockIdx.x * blockDim.x + threadIdx.x;
    if (i >= n4) return;
    float4 v = src[i];
    float s0, s1, s2, s3;
    uint32_t bw0 = pack_big(v.x, v.y, s0, s1);
    uint32_t bw1 = pack_big(v.z, v.w, s2, s3);
    uint32_t sw0 = pack_bf2(s0, s1);
    uint32_t sw1 = pack_bf2(s2, s3);
    *(uint2*)&dstb[(size_t)i * 4] = make_uint2(bw0, bw1);
    *(uint2*)&dsts[(size_t)i * 4] = make_uint2(sw0, sw1);
}

// ---------------- bf16x3 pipelined GEMM ---------------------------------------
// C = A[M,K] @ W[N,K]^T + bias (+ops). A,W pre-split bf16 (big/small).
// BM=128, BK=32, 256 threads (8 warps: 4M x 2N). Warp tile 32 x BN/2.
// smem rows padded to 80 bytes (32 bf16 data + 8 pad). 3-stage cp.async.
// MODE 0: bias -> fp32 C ; MODE 1: bias+gelu -> split bf16 (Cb,Cs)
// MODE 2: bias+res -> fp32 C
#define NSTAGE 3
template <int BN, int MODE>
__global__ void __launch_bounds__(256, 1)
k_gemm_bf3(const __nv_bfloat16* __restrict__ Ab_g, const __nv_bfloat16* __restrict__ As_g,
           const __nv_bfloat16* __restrict__ Wb_g, const __nv_bfloat16* __restrict__ Ws_g,
           const float* __restrict__ bias, const float* __restrict__ res,
           float* __restrict__ C, __nv_bfloat16* __restrict__ Cb,
           __nv_bfloat16* __restrict__ Cs, int Ncols, int K) {
    extern __shared__ char sh[];
    const uint32_t STAGE = (128 + BN) * 2 * 80;   // bytes per stage
    const uint32_t AOFF = 128 * 80;               // one A tile bytes
    const uint32_t WOFF = BN * 80;
    uint32_t sbase = (uint32_t)__cvta_generic_to_shared(sh);

    const int tid = threadIdx.x;
    const int wid = tid >> 5, lane = tid & 31;
    const int g = lane >> 2, t = lane & 3;
    const int lrow = lane & 7, seg = lane >> 3;
    const int warp_m = wid & 3, warp_n = wid >> 2;
    const int wm0 = warp_m * 32;
    const int wn0 = warp_n * (BN / 2);
    const int m0 = blockIdx.y * 128, n0 = blockIdx.x * BN;
    const int NI = BN / 16;
    const int NCH = (128 + BN) * 2 * 4;           // 16B chunks per stage
    const int nC = K >> 5;

    float acc[2][NI][4];
    #pragma unroll
    for (int mi = 0; mi < 2; mi++)
        #pragma unroll
        for (int ni = 0; ni < NI; ni++)
            #pragma unroll
            for (int j = 0; j < 4; j++) acc[mi][ni][j] = 0.f;

    auto load = [&](int c) {
        int k0 = c << 5;
        uint32_t base = sbase + (uint32_t)(c % NSTAGE) * STAGE;
        #pragma unroll
        for (int i = tid; i < NCH; i += 256) {
            const __nv_bfloat16* gsrc;
            uint32_t dst;
            if (i < 512) {
                int row = i >> 2, j = i & 3;
                gsrc = Ab_g + (size_t)(m0 + row) * K + k0 + j * 8;
                dst = base + row * 80 + j * 16;
            } else if (i < 1024) {
                int i2 = i - 512;
                int row = i2 >> 2, j = i2 & 3;
                gsrc = As_g + (size_t)(m0 + row) * K + k0 + j * 8;
                dst = base + AOFF + row * 80 + j * 16;
            } else if (i < 1024 + BN * 4) {
                int i2 = i - 1024;
                int row = i2 >> 2, j = i2 & 3;
                gsrc = Wb_g + (size_t)(n0 + row) * K + k0 + j * 8;
                dst = base + 2 * AOFF + row * 80 + j * 16;
            } else {
                int i2 = i - 1024 - BN * 4;
                int row = i2 >> 2, j = i2 & 3;
                gsrc = Ws_g + (size_t)(n0 + row) * K + k0 + j * 8;
                dst = base + 2 * AOFF + WOFF + row * 80 + j * 16;
            }
            CP_ASYNC16(dst, gsrc);
        }
        CP_COMMIT();
    };

    // prologue: fill NSTAGE-1 stages
    load(0);
    load(1);

    for (int c = 0; c < nC; c++) {
        if (c + NSTAGE - 1 < nC) load(c + NSTAGE - 1);
        else CP_COMMIT();
        asm volatile("cp.async.wait_group %0;" :: "n"(NSTAGE - 1));
        __syncthreads();

        uint32_t base = sbase + (uint32_t)(c % NSTAGE) * STAGE;
        uint32_t aB = base, aS = base + AOFF;
        uint32_t wB = base + 2 * AOFF, wS = wB + WOFF;

        #pragma unroll
        for (int ks = 0; ks < 2; ks++) {
            uint32_t ab[2][4], as_[2][4];
            #pragma unroll
            for (int mi = 0; mi < 2; mi++) {
                uint32_t off = (uint32_t)((wm0 + mi * 16 + (seg & 1) * 8 + lrow) * 80
                                          + ks * 32 + (seg >> 1) * 16);
                LDSM4(ab[mi][0], ab[mi][1], ab[mi][2], ab[mi][3], aB + off);
                LDSM4(as_[mi][0], as_[mi][1], as_[mi][2], as_[mi][3], aS + off);
            }
            uint32_t wb[NI][2], ws[NI][2];
            #pragma unroll
            for (int np = 0; np < NI / 2; np++) {
                uint32_t off = (uint32_t)((wn0 + np * 16 + (seg >> 1) * 8 + lrow) * 80
                                          + ks * 32 + (seg & 1) * 16);
                LDSM4(wb[2 * np][0], wb[2 * np][1], wb[2 * np + 1][0], wb[2 * np + 1][1], wB + off);
                LDSM4(ws[2 * np][0], ws[2 * np][1], ws[2 * np + 1][0], ws[2 * np + 1][1], wS + off);
            }
            #pragma unroll
            for (int ni = 0; ni < NI; ni++) {
                #pragma unroll
                for (int mi = 0; mi < 2; mi++) {
                    mma_bf16(acc[mi][ni], ab[mi], wb[ni][0], wb[ni][1]);
                    mma_bf16(acc[mi][ni], as_[mi], wb[ni][0], wb[ni][1]);
                    mma_bf16(acc[mi][ni], ab[mi], ws[ni][0], ws[ni][1]);
                }
            }
        }
        __syncthreads();
    }

    // epilogue: c0,c1 -> row g cols 2t,2t+1 ; c2,c3 -> row g+8
    #pragma unroll
    for (int mi = 0; mi < 2; mi++) {
        int r0 = m0 + wm0 + mi * 16 + g;
        int r1 = r0 + 8;
        #pragma unroll
        for (int ni = 0; ni < NI; ni++) {
            int n = n0 + wn0 + ni * 8 + 2 * t;
            float b0 = bias[n], b1 = bias[n + 1];
            float v0 = acc[mi][ni][0] + b0;
            float v1 = acc[mi][ni][1] + b1;
            float v2 = acc[mi][ni][2] + b0;
            float v3 = acc[mi][ni][3] + b1;
            if (MODE == 1) {
                v0 = 0.5f * v0 * (1.f + erff(v0 * 0.70710678118654752f));
                v1 = 0.5f * v1 * (1.f + erff(v1 * 0.70710678118654752f));
                v2 = 0.5f * v2 * (1.f + erff(v2 * 0.70710678118654752f));
                v3 = 0.5f * v3 * (1.f + erff(v3 * 0.70710678118654752f));
                float s0, s1, s2, s3;
                uint32_t bw0 = pack_big(v0, v1, s0, s1);
                uint32_t bw1 = pack_big(v2, v3, s2, s3);
                *(uint32_t*)&Cb[(size_t)r0 * Ncols + n] = bw0;
                *(uint32_t*)&Cb[(size_t)r1 * Ncols + n] = bw1;
                *(uint32_t*)&Cs[(size_t)r0 * Ncols + n] = pack_bf2(s0, s1);
                *(uint32_t*)&Cs[(size_t)r1 * Ncols + n] = pack_bf2(s2, s3);
            } else {
                if (MODE == 2) {
                    v0 += res[(size_t)r0 * Ncols + n];
                    v1 += res[(size_t)r0 * Ncols + n + 1];
                    v2 += res[(size_t)r1 * Ncols + n];
                    v3 += res[(size_t)r1 * Ncols + n + 1];
                }
                *(float2*)&C[(size_t)r0 * Ncols + n] = make_float2(v0, v1);
                *(float2*)&C[(size_t)r1 * Ncols + n] = make_float2(v2, v3);
            }
        }
    }
}

// ---------------- patchify ---------------------------------------------------
__global__ void k_patchify(const float* __restrict__ x,
                           const float* __restrict__ attn_mask,
                           const int*   __restrict__ yids,
                           const float* __restrict__ conv_w,
                           const float* __restrict__ conv_b,
                           const float* __restrict__ pex,
                           const float* __restrict__ ytab) {
    int bl = blockIdx.x;
    int b = bl / LL, l = bl % LL;
    int gh = l / GW, gw = l % GW;
    __shared__ float patch[QQ];
    const float* xrow = x + ((size_t)b * HIN + gh) * WIN + gw * QQ;
    for (int i = threadIdx.x; i < QQ; i += blockDim.x) patch[i] = xrow[i];
    __syncthreads();
    float am = attn_mask[b * LL + l];
    int yid = yids[b * LL + l];
    for (int d = threadIdx.x; d < DD; d += blockDim.x) {
        const float* w = conv_w + d * QQ;
        float acc = 0.f;
        #pragma unroll 4
        for (int q = 0; q < QQ; q++) acc += patch[q] * w[q];
        acc += conv_b[d];
        if (d < DH) acc += ytab[yid * DH + d];
        else        acc += am * pex[(gw + 1) * DH + (d - DH)];
        g_hfull[((size_t)b * LL + l) * DD + d] = acc;
    }
}

// ---------------- per-batch stable argsort + keep / mask build ---------------
__global__ void k_select(const float* __restrict__ noise,
                         const float* __restrict__ attn_mask) {
    int b = blockIdx.x;
    __shared__ float ns[LL];
    __shared__ int ids[LL];
    __shared__ unsigned char keep[LL];
    for (int i = threadIdx.x; i < LL; i += blockDim.x) { ns[i] = noise[b * LL + i]; keep[i] = 0; }
    __syncthreads();
    for (int i = threadIdx.x; i < LL; i += blockDim.x) {
        float vi = ns[i];
        int r = 0;
        for (int j = 0; j < LL; j++) {
            float vj = ns[j];
            r += (vj < vi) || (vj == vi && j < i);
        }
        ids[r] = i;
    }
    __syncthreads();
    for (int t = threadIdx.x; t < LEN_KEEP; t += blockDim.x) {
        g_idsk[b * LEN_KEEP + t] = ids[t];
        keep[ids[t]] = 1;
    }
    __syncthreads();
    for (int i = threadIdx.x; i < LL; i += blockDim.x) {
        if (keep[i]) {
            int pos = 0;
            for (int j = 0; j < i; j++) pos += keep[j];
            g_m[b * NTOK + 1 + pos] = attn_mask[b * LL + i];
        }
    }
    if (threadIdx.x == 0) g_m[b * NTOK] = 1.f;
}

// ---------------- gather kept tokens, prepend cls ----------------------------
__global__ void k_gather(const float* __restrict__ cls_token,
                         const float* __restrict__ pex) {
    int bt = blockIdx.x;
    int b = bt / NTOK, t = bt % NTOK;
    float* outp = g_carry + (size_t)bt * DD;
    if (t == 0) {
        for (int d = threadIdx.x; d < DD; d += blockDim.x)
            outp[d] = cls_token[d] + (d >= DH ? pex[d - DH] : 0.f);
    } else {
        int l = g_idsk[b * LEN_KEEP + (t - 1)];
        const float* src = g_hfull + ((size_t)b * LL + l) * DD;
        for (int d = threadIdx.x; d < DD; d += blockDim.x) outp[d] = src[d];
    }
}

// ---------------- layernorm (fp32 out, final) ---------------------------------
__global__ void k_ln(const float* __restrict__ in,
                     const float* __restrict__ w,
                     const float* __restrict__ bias,
                     float* __restrict__ out) {
    int r = blockIdx.x;
    const float* p = in + (size_t)r * DD;
    __shared__ float red[256];
    float s = 0.f;
    for (int d = threadIdx.x; d < DD; d += 256) s += p[d];
    red[threadIdx.x] = s; __syncthreads();
    for (int o = 128; o > 0; o >>= 1) {
        if (threadIdx.x < o) red[threadIdx.x] += red[threadIdx.x + o];
        __syncthreads();
    }
    float mu = red[0] * (1.f / DD);
    __syncthreads();
    float v = 0.f;
    for (int d = threadIdx.x; d < DD; d += 256) { float t = p[d] - mu; v += t * t; }
    red[threadIdx.x] = v; __syncthreads();
    for (int o = 128; o > 0; o >>= 1) {
        if (threadIdx.x < o) red[threadIdx.x] += red[threadIdx.x + o];
        __syncthreads();
    }
    float rstd = rsqrtf(red[0] * (1.f / DD) + EPS_LN);
    for (int d = threadIdx.x; d < DD; d += 256)
        out[(size_t)r * DD + d] = (p[d] - mu) * rstd * w[d] + bias[d];
}

// ---------------- layernorm (split bf16 out) ----------------------------------
__global__ void k_ln_sp(const float* __restrict__ in,
                        const float* __restrict__ w,
                        const float* __restrict__ bias) {
    int r = blockIdx.x;
    const float* p = in + (size_t)r * DD;
    __shared__ float red[256];
    float s = 0.f;
    for (int d = threadIdx.x; d < DD; d += 256) s += p[d];
    red[threadIdx.x] = s; __syncthreads();
    for (int o = 128; o > 0; o >>= 1) {
        if (threadIdx.x < o) red[threadIdx.x] += red[threadIdx.x + o];
        __syncthreads();
    }
    float mu = red[0] * (1.f / DD);
    __syncthreads();
    float v = 0.f;
    for (int d = threadIdx.x; d < DD; d += 256) { float t = p[d] - mu; v += t * t; }
    red[threadIdx.x] = v; __syncthreads();
    for (int o = 128; o > 0; o >>= 1) {
        if (threadIdx.x < o) red[threadIdx.x] += red[threadIdx.x + o];
        __syncthreads();
    }
    float rstd = rsqrtf(red[0] * (1.f / DD) + EPS_LN);
    for (int d = threadIdx.x; d < DD; d += 256) {
        float val = (p[d] - mu) * rstd * w[d] + bias[d];
        __nv_bfloat16 big = __float2bfloat16(val);
        g_actb[(size_t)r * DD + d] = big;
        g_acts[(size_t)r * DD + d] = __float2bfloat16(val - __bfloat162float(big));
    }
}

// ---------------- attention: scores + global max -----------------------------
__global__ void k_reset_gmax() { g_gmax = 0u; }

__global__ void k_scores() {
    int idx = blockIdx.x;
    int n = idx % NTOK;
    int bh = idx / NTOK;
    int h = bh % NHD, b = bh / NHD;
    __shared__ float qsh[HD];
    __shared__ float red[128];
    const float* qp = g_qkv + (size_t)(b * NTOK + n) * (3 * DD) + h * HD;
    if (threadIdx.x < HD) qsh[threadIdx.x] = qp[threadIdx.x];
    __syncthreads();
    float mn = g_m[b * NTOK + n];
    float lmax = -3.4e38f;
    int m = threadIdx.x;
    if (m < NTOK) {
        const float* kp = g_qkv + (size_t)(b * NTOK + m) * (3 * DD) + DD + h * HD;
        float dot = 0.f;
        #pragma unroll
        for (int d = 0; d < HD; d++) dot += qsh[d] * kp[d];
        float logit = dot * SCALE;
        float mm = mn * g_m[b * NTOK + m];
        if (mm == 0.f) logit = -INFINITY; else lmax = logit;
        g_att[(size_t)idx * NTOK + m] = logit;
    }
    red[threadIdx.x] = lmax; __syncthreads();
    for (int o = 64; o > 0; o >>= 1) {
        if (threadIdx.x < o) red[threadIdx.x] = fmaxf(red[threadIdx.x], red[threadIdx.x + o]);
        __syncthreads();
    }
    if (threadIdx.x == 0 && red[0] > -3.3e38f) atomicMax(&g_gmax, fenc(red[0]));
}

// ---------------- softmax (global-max variant) + AV -> split bf16 -------------
__global__ void k_softmax_av() {
    int idx = blockIdx.x;
    int n = idx % NTOK;
    int bh = idx / NTOK;
    int h = bh % NHD, b = bh / NHD;
    __shared__ float p[NTOK];
    __shared__ float red[128];
    float g = fdec(g_gmax);
    float e = 0.f;
    if (threadIdx.x < NTOK) {
        e = expf(g_att[(size_t)idx * NTOK + threadIdx.x] - g);
        p[threadIdx.x] = e;
    }
    red[threadIdx.x] = e; __syncthreads();
    for (int o = 64; o > 0; o >>= 1) {
        if (threadIdx.x < o) red[threadIdx.x] += red[threadIdx.x + o];
        __syncthreads();
    }
    float inv = 1.f / (red[0] + 1e-9f);
    if (threadIdx.x < HD) {
        const float* vp = g_qkv + (size_t)(b * NTOK) * (3 * DD) + 2 * DD + h * HD + threadIdx.x;
        float acc = 0.f;
        for (int m2 = 0; m2 < NTOK; m2++) acc += p[m2] * vp[(size_t)m2 * 3 * DD];
        float val = acc * inv;
        __nv_bfloat16 big = __float2bfloat16(val);
        size_t o2 = (size_t)(b * NTOK + n) * DD + h * HD + threadIdx.x;
        g_actb[o2] = big;
        g_acts[o2] = __float2bfloat16(val - __bfloat162float(big));
    }
}

// ---------------- launch -----------------------------------------------------
extern "C" void kernel_launch(void* const* d_in, const int* in_sizes, int n_in,
                              void* d_out, int out_size) {
    const float* x         = (const float*)d_in[0];
    const float* attn_mask = (const float*)d_in[1];
    const int*   yids      = (const int*)  d_in[2];
    const float* noise     = (const float*)d_in[3];
    const float* conv_w    = (const float*)d_in[4];
    const float* conv_b    = (const float*)d_in[5];
    const float* pex       = (const float*)d_in[6];
    const float* ytab      = (const float*)d_in[7];
    const float* cls       = (const float*)d_in[8];
    const float* qkv_w     = (const float*)d_in[9];
    const float* qkv_b     = (const float*)d_in[10];
    const float* proj_w    = (const float*)d_in[11];
    const float* proj_b    = (const float*)d_in[12];
    const float* ln1_w     = (const float*)d_in[13];
    const float* ln1_b     = (const float*)d_in[14];
    const float* ln2_w     = (const float*)d_in[15];
    const float* ln2_b     = (const float*)d_in[16];
    const float* fc1_w     = (const float*)d_in[17];
    const float* fc1_b     = (const float*)d_in[18];
    const float* fc2_w     = (const float*)d_in[19];
    const float* fc2_b     = (const float*)d_in[20];
    const float* norm_w    = (const float*)d_in[21];
    const float* norm_b    = (const float*)d_in[22];
    float* out = (float*)d_out;

    float *carry, *qkv;
    __nv_bfloat16 *actb, *acts, *hidb, *hids;
    __nv_bfloat16 *wqb, *wqs, *wpb, *wps, *w1b, *w1s, *w2b, *w2s;
    cudaGetSymbolAddress((void**)&carry, g_carry);
    cudaGetSymbolAddress((void**)&qkv,   g_qkv);
    cudaGetSymbolAddress((void**)&actb,  g_actb);
    cudaGetSymbolAddress((void**)&acts,  g_acts);
    cudaGetSymbolAddress((void**)&hidb,  g_hidb);
    cudaGetSymbolAddress((void**)&hids,  g_hids);
    cudaGetSymbolAddress((void**)&wqb,   g_wqb);
    cudaGetSymbolAddress((void**)&wqs,   g_wqs);
    cudaGetSymbolAddress((void**)&wpb,   g_wpb);
    cudaGetSymbolAddress((void**)&wps,   g_wps);
    cudaGetSymbolAddress((void**)&w1b,   g_w1b);
    cudaGetSymbolAddress((void**)&w1s,   g_w1s);
    cudaGetSymbolAddress((void**)&w2b,   g_w2b);
    cudaGetSymbolAddress((void**)&w2s,   g_w2s);

    const int SM128 = NSTAGE * (128 + 128) * 2 * 80;  // 122880
    const int SM64  = NSTAGE * (128 + 64)  * 2 * 80;  // 92160
    cudaFuncSetAttribute(k_gemm_bf3<128, 0>, cudaFuncAttributeMaxDynamicSharedMemorySize, SM128);
    cudaFuncSetAttribute(k_gemm_bf3<128, 1>, cudaFuncAttributeMaxDynamicSharedMemorySize, SM128);
    cudaFuncSetAttribute(k_gemm_bf3<64, 2>,  cudaFuncAttributeMaxDynamicSharedMemorySize, SM64);

    const int MT = M_PAD / 128;  // 10

    // weight pre-split (deterministic, every launch)
    k_split<<<(QWN / 4 + 255) / 256, 256>>>((const float4*)qkv_w,  wqb, wqs, QWN / 4);
    k_split<<<(PWN / 4 + 255) / 256, 256>>>((const float4*)proj_w, wpb, wps, PWN / 4);
    k_split<<<(F1N / 4 + 255) / 256, 256>>>((const float4*)fc1_w,  w1b, w1s, F1N / 4);
    k_split<<<(F2N / 4 + 255) / 256, 256>>>((const float4*)fc2_w,  w2b, w2s, F2N / 4);

    // prologue
    k_patchify<<<BB * LL, 256>>>(x, attn_mask, yids, conv_w, conv_b, pex, ytab);
    k_select<<<BB, 256>>>(noise, attn_mask);
    k_gather<<<BB * NTOK, 256>>>(cls, pex);

    for (int l = 0; l < DEPTH; l++) {
        const float* qb  = qkv_b  + (size_t)l * 3 * DD;
        const float* pb  = proj_b + (size_t)l * DD;
        const float* l1w = ln1_w + l * DD; const float* l1b = ln1_b + l * DD;
        const float* l2w = ln2_w + l * DD; const float* l2b = ln2_b + l * DD;
        const float* f1b = fc1_b + (size_t)l * MLPD;
        const float* f2b = fc2_b + (size_t)l * DD;
        __nv_bfloat16* lwqb = wqb + (size_t)l * 3 * DD * DD;
        __nv_bfloat16* lwqs = wqs + (size_t)l * 3 * DD * DD;
        __nv_bfloat16* lwpb = wpb + (size_t)l * DD * DD;
        __nv_bfloat16* lwps = wps + (size_t)l * DD * DD;
        __nv_bfloat16* lw1b = w1b + (size_t)l * MLPD * DD;
        __nv_bfloat16* lw1s = w1s + (size_t)l * MLPD * DD;
        __nv_bfloat16* lw2b = w2b + (size_t)l * DD * MLPD;
        __nv_bfloat16* lw2s = w2s + (size_t)l * DD * MLPD;

        k_ln_sp<<<MROWS, 256>>>(carry, l1w, l1b);
        k_gemm_bf3<128, 0><<<dim3(3 * DD / 128, MT), 256, SM128>>>(
            actb, acts, lwqb, lwqs, qb, nullptr, qkv, nullptr, nullptr, 3 * DD, DD);
        k_reset_gmax<<<1, 1>>>();
        k_scores<<<BB * NHD * NTOK, 128>>>();
        k_softmax_av<<<BB * NHD * NTOK, 128>>>();
        k_gemm_bf3<64, 2><<<dim3(DD / 64, MT), 256, SM64>>>(
            actb, acts, lwpb, lwps, pb, carry, carry, nullptr, nullptr, DD, DD);
        k_ln_sp<<<MROWS, 256>>>(carry, l2w, l2b);
        k_gemm_bf3<128, 1><<<dim3(MLPD / 128, MT), 256, SM128>>>(
            actb, acts, lw1b, lw1s, f1b, nullptr, nullptr, hidb, hids, MLPD, DD);
        k_gemm_bf3<64, 2><<<dim3(DD / 64, MT), 256, SM64>>>(
            hidb, hids, lw2b, lw2s, f2b, carry, carry, nullptr, nullptr, DD, MLPD);
    }

    k_ln<<<MROWS, 256>>>(carry, norm_w, norm_b, out);
}

// round 7
// speedup vs baseline: 2.2639x; 1.0017x over previous
#include <cuda_runtime.h>
#include <cuda_bf16.h>
#include <math.h>
#include <cstdint>

#define BB   16
#define HIN  12
#define WIN  2500
#define QQ   100
#define GW   25
#define LL   300
#define LEN_KEEP 75
#define NTOK 76
#define DD   768
#define DH   384
#define NHD  12
#define HD   64
#define DEPTH 12
#define MLPD 3072
#define SCALE 0.125f
#define EPS_LN 1e-5f
#define MROWS (BB * NTOK)     // 1216
#define M_PAD 1280            // 10 tiles of 128

#define QWN  (DEPTH * 3 * DD * DD)
#define PWN  (DEPTH * DD * DD)
#define F1N  (DEPTH * MLPD * DD)
#define F2N  (DEPTH * DD * MLPD)

// ---------------- scratch (device globals; no allocation allowed) -----------
__device__ float g_hfull[BB * LL * DD];
__device__ float g_carry[M_PAD * DD];
__device__ float g_qkv[M_PAD * 3 * DD];
__device__ float g_att[BB * NHD * NTOK * NTOK];
__device__ int   g_idsk[BB * LEN_KEEP];
__device__ float g_m[BB * NTOK];
__device__ unsigned g_gmax;

// split activations (big/small bf16)
__device__ __nv_bfloat16 g_actb[M_PAD * DD],   g_acts[M_PAD * DD];
__device__ __nv_bfloat16 g_hidb[M_PAD * MLPD], g_hids[M_PAD * MLPD];
// split weights
__device__ __nv_bfloat16 g_wqb[QWN], g_wqs[QWN];
__device__ __nv_bfloat16 g_wpb[PWN], g_wps[PWN];
__device__ __nv_bfloat16 g_w1b[F1N], g_w1s[F1N];
__device__ __nv_bfloat16 g_w2b[F2N], g_w2s[F2N];

// monotone float<->uint encoding for atomicMax on floats
__device__ __forceinline__ unsigned fenc(float f) {
    unsigned u = __float_as_uint(f);
    return (u & 0x80000000u) ? ~u : (u | 0x80000000u);
}
__device__ __forceinline__ float fdec(unsigned u) {
    return (u & 0x80000000u) ? __uint_as_float(u & 0x7fffffffu) : __uint_as_float(~u);
}

// ---------------- asm helpers -------------------------------------------------
#define CP_ASYNC16(dst, src) \
    asm volatile("cp.async.cg.shared.global [%0], [%1], 16;" :: "r"(dst), "l"(src))
#define CP_COMMIT() asm volatile("cp.async.commit_group;" ::: "memory")
#define LDSM4(r0, r1, r2, r3, addr)                                          \
    asm volatile("ldmatrix.sync.aligned.m8n8.x4.shared.b16 {%0,%1,%2,%3}, [%4];" \
        : "=r"(r0), "=r"(r1), "=r"(r2), "=r"(r3) : "r"(addr))

__device__ __forceinline__ void mma_bf16(float* d, const uint32_t* a,
                                         uint32_t b0, uint32_t b1) {
    asm volatile(
        "mma.sync.aligned.m16n8k16.row.col.f32.bf16.bf16.f32 "
        "{%0,%1,%2,%3}, {%4,%5,%6,%7}, {%8,%9}, {%0,%1,%2,%3};"
        : "+f"(d[0]), "+f"(d[1]), "+f"(d[2]), "+f"(d[3])
        : "r"(a[0]), "r"(a[1]), "r"(a[2]), "r"(a[3]), "r"(b0), "r"(b1));
}

__device__ __forceinline__ uint32_t pack_big(float v0, float v1, float& r0, float& r1) {
    __nv_bfloat16 b0 = __float2bfloat16(v0);
    __nv_bfloat16 b1 = __float2bfloat16(v1);
    r0 = v0 - __bfloat162float(b0);
    r1 = v1 - __bfloat162float(b1);
    return (uint32_t)__bfloat16_as_ushort(b0) | ((uint32_t)__bfloat16_as_ushort(b1) << 16);
}
__device__ __forceinline__ uint32_t pack_bf2(float v0, float v1) {
    __nv_bfloat16 b0 = __float2bfloat16(v0);
    __nv_bfloat16 b1 = __float2bfloat16(v1);
    return (uint32_t)__bfloat16_as_ushort(b0) | ((uint32_t)__bfloat16_as_ushort(b1) << 16);
}

// ---------------- weight split kernel -----------------------------------------
__global__ void k_split(const float4* __restrict__ src,
                        __nv_bfloat16* __restrict__ dstb,
                        __nv_bfloat16* __restrict__ dsts, int n4) {
    int i = blockIdx.x * blockDim.x + threadIdx.x;
    if (i >= n4) return;
    float4 v = src[i];
    float s0, s1, s2, s3;
    uint32_t bw0 = pack_big(v.x, v.y, s0, s1);
    uint32_t bw1 = pack_big(v.z, v.w, s2, s3);
    uint32_t sw0 = pack_bf2(s0, s1);
    uint32_t sw1 = pack_bf2(s2, s3);
    *(uint2*)&dstb[(size_t)i * 4] = make_uint2(bw0, bw1);
    *(uint2*)&dsts[(size_t)i * 4] = make_uint2(sw0, sw1);
}

// ---------------- bf16x3 pipelined GEMM ---------------------------------------
// C = A[M,K] @ W[N,K]^T + bias (+ops). A,W pre-split bf16 (big/small).
// BM=128, BK=32, 256 threads (8 warps: 4M x 2N). Warp tile 32 x BN/2.
// smem rows padded to 80 bytes. 3-stage cp.async.
// MMAs issued TERM-MAJOR (all big*big, then small*big, then big*small) so
// same-accumulator reuse distance is 2*NI independent MMAs (no RAW stalls).
// MODE 0: bias -> fp32 C ; MODE 1: bias+gelu -> split bf16 (Cb,Cs)
// MODE 2: bias+res -> fp32 C
#define NSTAGE 3
template <int BN, int MODE>
__global__ void __launch_bounds__(256, 1)
k_gemm_bf3(const __nv_bfloat16* __restrict__ Ab_g, const __nv_bfloat16* __restrict__ As_g,
           const __nv_bfloat16* __restrict__ Wb_g, const __nv_bfloat16* __restrict__ Ws_g,
           const float* __restrict__ bias, const float* __restrict__ res,
           float* __restrict__ C, __nv_bfloat16* __restrict__ Cb,
           __nv_bfloat16* __restrict__ Cs, int Ncols, int K) {
    extern __shared__ char sh[];
    const uint32_t STAGE = (128 + BN) * 2 * 80;   // bytes per stage
    const uint32_t AOFF = 128 * 80;               // one A tile bytes
    const uint32_t WOFF = BN * 80;
    uint32_t sbase = (uint32_t)__cvta_generic_to_shared(sh);

    const int tid = threadIdx.x;
    const int wid = tid >> 5, lane = tid & 31;
    const int g = lane >> 2, t = lane & 3;
    const int lrow = lane & 7, seg = lane >> 3;
    const int warp_m = wid & 3, warp_n = wid >> 2;
    const int wm0 = warp_m * 32;
    const int wn0 = warp_n * (BN / 2);
    const int m0 = blockIdx.y * 128, n0 = blockIdx.x * BN;
    const int NI = BN / 16;
    const int NCH = (128 + BN) * 2 * 4;           // 16B chunks per stage
    const int nC = K >> 5;

    float acc[2][NI][4];
    #pragma unroll
    for (int mi = 0; mi < 2; mi++)
        #pragma unroll
        for (int ni = 0; ni < NI; ni++)
            #pragma unroll
            for (int j = 0; j < 4; j++) acc[mi][ni][j] = 0.f;

    auto load = [&](int c) {
        int k0 = c << 5;
        uint32_t base = sbase + (uint32_t)(c % NSTAGE) * STAGE;
        #pragma unroll
        for (int i = tid; i < NCH; i += 256) {
            const __nv_bfloat16* gsrc;
            uint32_t dst;
            if (i < 512) {
                int row = i >> 2, j = i & 3;
                gsrc = Ab_g + (size_t)(m0 + row) * K + k0 + j * 8;
                dst = base + row * 80 + j * 16;
            } else if (i < 1024) {
                int i2 = i - 512;
                int row = i2 >> 2, j = i2 & 3;
                gsrc = As_g + (size_t)(m0 + row) * K + k0 + j * 8;
                dst = base + AOFF + row * 80 + j * 16;
            } else if (i < 1024 + BN * 4) {
                int i2 = i - 1024;
                int row = i2 >> 2, j = i2 & 3;
                gsrc = Wb_g + (size_t)(n0 + row) * K + k0 + j * 8;
                dst = base + 2 * AOFF + row * 80 + j * 16;
            } else {
                int i2 = i - 1024 - BN * 4;
                int row = i2 >> 2, j = i2 & 3;
                gsrc = Ws_g + (size_t)(n0 + row) * K + k0 + j * 8;
                dst = base + 2 * AOFF + WOFF + row * 80 + j * 16;
            }
            CP_ASYNC16(dst, gsrc);
        }
        CP_COMMIT();
    };

    // prologue: fill NSTAGE-1 stages
    load(0);
    load(1);

    for (int c = 0; c < nC; c++) {
        if (c + NSTAGE - 1 < nC) load(c + NSTAGE - 1);
        else CP_COMMIT();
        asm volatile("cp.async.wait_group %0;" :: "n"(NSTAGE - 1));
        __syncthreads();

        uint32_t base = sbase + (uint32_t)(c % NSTAGE) * STAGE;
        uint32_t aB = base, aS = base + AOFF;
        uint32_t wB = base + 2 * AOFF, wS = wB + WOFF;

        #pragma unroll
        for (int ks = 0; ks < 2; ks++) {
            uint32_t ab[2][4], as_[2][4];
            #pragma unroll
            for (int mi = 0; mi < 2; mi++) {
                uint32_t off = (uint32_t)((wm0 + mi * 16 + (seg & 1) * 8 + lrow) * 80
                                          + ks * 32 + (seg >> 1) * 16);
                LDSM4(ab[mi][0], ab[mi][1], ab[mi][2], ab[mi][3], aB + off);
                LDSM4(as_[mi][0], as_[mi][1], as_[mi][2], as_[mi][3], aS + off);
            }
            uint32_t wb[NI][2], ws[NI][2];
            #pragma unroll
            for (int np = 0; np < NI / 2; np++) {
                uint32_t off = (uint32_t)((wn0 + np * 16 + (seg >> 1) * 8 + lrow) * 80
                                          + ks * 32 + (seg & 1) * 16);
                LDSM4(wb[2 * np][0], wb[2 * np][1], wb[2 * np + 1][0], wb[2 * np + 1][1], wB + off);
                LDSM4(ws[2 * np][0], ws[2 * np][1], ws[2 * np + 1][0], ws[2 * np + 1][1], wS + off);
            }
            // term-major: maximize independent MMAs between acc reuse
            #pragma unroll
            for (int ni = 0; ni < NI; ni++)
                #pragma unroll
                for (int mi = 0; mi < 2; mi++)
                    mma_bf16(acc[mi][ni], ab[mi], wb[ni][0], wb[ni][1]);
            #pragma unroll
            for (int ni = 0; ni < NI; ni++)
                #pragma unroll
                for (int mi = 0; mi < 2; mi++)
                    mma_bf16(acc[mi][ni], as_[mi], wb[ni][0], wb[ni][1]);
            #pragma unroll
            for (int ni = 0; ni < NI; ni++)
                #pragma unroll
                for (int mi = 0; mi < 2; mi++)
                    mma_bf16(acc[mi][ni], ab[mi], ws[ni][0], ws[ni][1]);
        }
        __syncthreads();
    }

    // epilogue: c0,c1 -> row g cols 2t,2t+1 ; c2,c3 -> row g+8
    #pragma unroll
    for (int mi = 0; mi < 2; mi++) {
        int r0 = m0 + wm0 + mi * 16 + g;
        int r1 = r0 + 8;
        #pragma unroll
        for (int ni = 0; ni < NI; ni++) {
            int n = n0 + wn0 + ni * 8 + 2 * t;
            float b0 = bias[n], b1 = bias[n + 1];
            float v0 = acc[mi][ni][0] + b0;
            float v1 = acc[mi][ni][1] + b1;
            float v2 = acc[mi][ni][2] + b0;
            float v3 = acc[mi][ni][3] + b1;
            if (MODE == 1) {
                v0 = 0.5f * v0 * (1.f + erff(v0 * 0.70710678118654752f));
                v1 = 0.5f * v1 * (1.f + erff(v1 * 0.70710678118654752f));
                v2 = 0.5f * v2 * (1.f + erff(v2 * 0.70710678118654752f));
                v3 = 0.5f * v3 * (1.f + erff(v3 * 0.70710678118654752f));
                float s0, s1, s2, s3;
                uint32_t bw0 = pack_big(v0, v1, s0, s1);
                uint32_t bw1 = pack_big(v2, v3, s2, s3);
                *(uint32_t*)&Cb[(size_t)r0 * Ncols + n] = bw0;
                *(uint32_t*)&Cb[(size_t)r1 * Ncols + n] = bw1;
                *(uint32_t*)&Cs[(size_t)r0 * Ncols + n] = pack_bf2(s0, s1);
                *(uint32_t*)&Cs[(size_t)r1 * Ncols + n] = pack_bf2(s2, s3);
            } else {
                if (MODE == 2) {
                    v0 += res[(size_t)r0 * Ncols + n];
                    v1 += res[(size_t)r0 * Ncols + n + 1];
                    v2 += res[(size_t)r1 * Ncols + n];
                    v3 += res[(size_t)r1 * Ncols + n + 1];
                }
                *(float2*)&C[(size_t)r0 * Ncols + n] = make_float2(v0, v1);
                *(float2*)&C[(size_t)r1 * Ncols + n] = make_float2(v2, v3);
            }
        }
    }
}

// ---------------- patchify ---------------------------------------------------
__global__ void k_patchify(const float* __restrict__ x,
                           const float* __restrict__ attn_mask,
                           const int*   __restrict__ yids,
                           const float* __restrict__ conv_w,
                           const float* __restrict__ conv_b,
                           const float* __restrict__ pex,
                           const float* __restrict__ ytab) {
    int bl = blockIdx.x;
    int b = bl / LL, l = bl % LL;
    int gh = l / GW, gw = l % GW;
    __shared__ float patch[QQ];
    const float* xrow = x + ((size_t)b * HIN + gh) * WIN + gw * QQ;
    for (int i = threadIdx.x; i < QQ; i += blockDim.x) patch[i] = xrow[i];
    __syncthreads();
    float am = attn_mask[b * LL + l];
    int yid = yids[b * LL + l];
    for (int d = threadIdx.x; d < DD; d += blockDim.x) {
        const float* w = conv_w + d * QQ;
        float acc = 0.f;
        #pragma unroll 4
        for (int q = 0; q < QQ; q++) acc += patch[q] * w[q];
        acc += conv_b[d];
        if (d < DH) acc += ytab[yid * DH + d];
        else        acc += am * pex[(gw + 1) * DH + (d - DH)];
        g_hfull[((size_t)b * LL + l) * DD + d] = acc;
    }
}

// ---------------- per-batch stable argsort + keep / mask build ---------------
__global__ void k_select(const float* __restrict__ noise,
                         const float* __restrict__ attn_mask) {
    int b = blockIdx.x;
    __shared__ float ns[LL];
    __shared__ int ids[LL];
    __shared__ unsigned char keep[LL];
    for (int i = threadIdx.x; i < LL; i += blockDim.x) { ns[i] = noise[b * LL + i]; keep[i] = 0; }
    __syncthreads();
    for (int i = threadIdx.x; i < LL; i += blockDim.x) {
        float vi = ns[i];
        int r = 0;
        for (int j = 0; j < LL; j++) {
            float vj = ns[j];
            r += (vj < vi) || (vj == vi && j < i);
        }
        ids[r] = i;
    }
    __syncthreads();
    for (int t = threadIdx.x; t < LEN_KEEP; t += blockDim.x) {
        g_idsk[b * LEN_KEEP + t] = ids[t];
        keep[ids[t]] = 1;
    }
    __syncthreads();
    for (int i = threadIdx.x; i < LL; i += blockDim.x) {
        if (keep[i]) {
            int pos = 0;
            for (int j = 0; j < i; j++) pos += keep[j];
            g_m[b * NTOK + 1 + pos] = attn_mask[b * LL + i];
        }
    }
    if (threadIdx.x == 0) g_m[b * NTOK] = 1.f;
}

// ---------------- gather kept tokens, prepend cls ----------------------------
__global__ void k_gather(const float* __restrict__ cls_token,
                         const float* __restrict__ pex) {
    int bt = blockIdx.x;
    int b = bt / NTOK, t = bt % NTOK;
    float* outp = g_carry + (size_t)bt * DD;
    if (t == 0) {
        for (int d = threadIdx.x; d < DD; d += blockDim.x)
            outp[d] = cls_token[d] + (d >= DH ? pex[d - DH] : 0.f);
    } else {
        int l = g_idsk[b * LEN_KEEP + (t - 1)];
        const float* src = g_hfull + ((size_t)b * LL + l) * DD;
        for (int d = threadIdx.x; d < DD; d += blockDim.x) outp[d] = src[d];
    }
}

// ---------------- layernorm (fp32 out, final) ---------------------------------
__global__ void k_ln(const float* __restrict__ in,
                     const float* __restrict__ w,
                     const float* __restrict__ bias,
                     float* __restrict__ out) {
    int r = blockIdx.x;
    const float* p = in + (size_t)r * DD;
    __shared__ float red[256];
    float s = 0.f;
    for (int d = threadIdx.x; d < DD; d += 256) s += p[d];
    red[threadIdx.x] = s; __syncthreads();
    for (int o = 128; o > 0; o >>= 1) {
        if (threadIdx.x < o) red[threadIdx.x] += red[threadIdx.x + o];
        __syncthreads();
    }
    float mu = red[0] * (1.f / DD);
    __syncthreads();
    float v = 0.f;
    for (int d = threadIdx.x; d < DD; d += 256) { float t = p[d] - mu; v += t * t; }
    red[threadIdx.x] = v; __syncthreads();
    for (int o = 128; o > 0; o >>= 1) {
        if (threadIdx.x < o) red[threadIdx.x] += red[threadIdx.x + o];
        __syncthreads();
    }
    float rstd = rsqrtf(red[0] * (1.f / DD) + EPS_LN);
    for (int d = threadIdx.x; d < DD; d += 256)
        out[(size_t)r * DD + d] = (p[d] - mu) * rstd * w[d] + bias[d];
}

// ---------------- layernorm (split bf16 out; also resets g_gmax) --------------
__global__ void k_ln_sp(const float* __restrict__ in,
                        const float* __restrict__ w,
                        const float* __restrict__ bias) {
    int r = blockIdx.x;
    if (r == 0 && threadIdx.x == 0) g_gmax = 0u;
    const float* p = in + (size_t)r * DD;
    __shared__ float red[256];
    float s = 0.f;
    for (int d = threadIdx.x; d < DD; d += 256) s += p[d];
    red[threadIdx.x] = s; __syncthreads();
    for (int o = 128; o > 0; o >>= 1) {
        if (threadIdx.x < o) red[threadIdx.x] += red[threadIdx.x + o];
        __syncthreads();
    }
    float mu = red[0] * (1.f / DD);
    __syncthreads();
    float v = 0.f;
    for (int d = threadIdx.x; d < DD; d += 256) { float t = p[d] - mu; v += t * t; }
    red[threadIdx.x] = v; __syncthreads();
    for (int o = 128; o > 0; o >>= 1) {
        if (threadIdx.x < o) red[threadIdx.x] += red[threadIdx.x + o];
        __syncthreads();
    }
    float rstd = rsqrtf(red[0] * (1.f / DD) + EPS_LN);
    for (int d = threadIdx.x; d < DD; d += 256) {
        float val = (p[d] - mu) * rstd * w[d] + bias[d];
        __nv_bfloat16 big = __float2bfloat16(val);
        g_actb[(size_t)r * DD + d] = big;
        g_acts[(size_t)r * DD + d] = __float2bfloat16(val - __bfloat162float(big));
    }
}

// ---------------- attention: scores + global max -----------------------------
__global__ void k_scores() {
    int idx = blockIdx.x;
    int n = idx % NTOK;
    int bh = idx / NTOK;
    int h = bh % NHD, b = bh / NHD;
    __shared__ float qsh[HD];
    __shared__ float red[128];
    const float* qp = g_qkv + (size_t)(b * NTOK + n) * (3 * DD) + h * HD;
    if (threadIdx.x < HD) qsh[threadIdx.x] = qp[threadIdx.x];
    __syncthreads();
    float mn = g_m[b * NTOK + n];
    float lmax = -3.4e38f;
    int m = threadIdx.x;
    if (m < NTOK) {
        const float* kp = g_qkv + (size_t)(b * NTOK + m) * (3 * DD) + DD + h * HD;
        float dot = 0.f;
        #pragma unroll
        for (int d = 0; d < HD; d++) dot += qsh[d] * kp[d];
        float logit = dot * SCALE;
        float mm = mn * g_m[b * NTOK + m];
        if (mm == 0.f) logit = -INFINITY; else lmax = logit;
        g_att[(size_t)idx * NTOK + m] = logit;
    }
    red[threadIdx.x] = lmax; __syncthreads();
    for (int o = 64; o > 0; o >>= 1) {
        if (threadIdx.x < o) red[threadIdx.x] = fmaxf(red[threadIdx.x], red[threadIdx.x + o]);
        __syncthreads();
    }
    if (threadIdx.x == 0 && red[0] > -3.3e38f) atomicMax(&g_gmax, fenc(red[0]));
}

// ---------------- softmax (global-max variant) + AV -> split bf16 -------------
__global__ void k_softmax_av() {
    int idx = blockIdx.x;
    int n = idx % NTOK;
    int bh = idx / NTOK;
    int h = bh % NHD, b = bh / NHD;
    __shared__ float p[NTOK];
    __shared__ float red[128];
    float g = fdec(g_gmax);
    float e = 0.f;
    if (threadIdx.x < NTOK) {
        e = expf(g_att[(size_t)idx * NTOK + threadIdx.x] - g);
        p[threadIdx.x] = e;
    }
    red[threadIdx.x] = e; __syncthreads();
    for (int o = 64; o > 0; o >>= 1) {
        if (threadIdx.x < o) red[threadIdx.x] += red[threadIdx.x + o];
        __syncthreads();
    }
    float inv = 1.f / (red[0] + 1e-9f);
    if (threadIdx.x < HD) {
        const float* vp = g_qkv + (size_t)(b * NTOK) * (3 * DD) + 2 * DD + h * HD + threadIdx.x;
        float acc = 0.f;
        for (int m2 = 0; m2 < NTOK; m2++) acc += p[m2] * vp[(size_t)m2 * 3 * DD];
        float val = acc * inv;
        __nv_bfloat16 big = __float2bfloat16(val);
        size_t o2 = (size_t)(b * NTOK + n) * DD + h * HD + threadIdx.x;
        g_actb[o2] = big;
        g_acts[o2] = __float2bfloat16(val - __bfloat162float(big));
    }
}

// ---------------- launch -----------------------------------------------------
extern "C" void kernel_launch(void* const* d_in, const int* in_sizes, int n_in,
                              void* d_out, int out_size) {
    const float* x         = (const float*)d_in[0];
    const float* attn_mask = (const float*)d_in[1];
    const int*   yids      = (const int*)  d_in[2];
    const float* noise     = (const float*)d_in[3];
    const float* conv_w    = (const float*)d_in[4];
    const float* conv_b    = (const float*)d_in[5];
    const float* pex       = (const float*)d_in[6];
    const float* ytab      = (const float*)d_in[7];
    const float* cls       = (const float*)d_in[8];
    const float* qkv_w     = (const float*)d_in[9];
    const float* qkv_b     = (const float*)d_in[10];
    const float* proj_w    = (const float*)d_in[11];
    const float* proj_b    = (const float*)d_in[12];
    const float* ln1_w     = (const float*)d_in[13];
    const float* ln1_b     = (const float*)d_in[14];
    const float* ln2_w     = (const float*)d_in[15];
    const float* ln2_b     = (const float*)d_in[16];
    const float* fc1_w     = (const float*)d_in[17];
    const float* fc1_b     = (const float*)d_in[18];
    const float* fc2_w     = (const float*)d_in[19];
    const float* fc2_b     = (const float*)d_in[20];
    const float* norm_w    = (const float*)d_in[21];
    const float* norm_b    = (const float*)d_in[22];
    float* out = (float*)d_out;

    float *carry, *qkv;
    __nv_bfloat16 *actb, *acts, *hidb, *hids;
    __nv_bfloat16 *wqb, *wqs, *wpb, *wps, *w1b, *w1s, *w2b, *w2s;
    cudaGetSymbolAddress((void**)&carry, g_carry);
    cudaGetSymbolAddress((void**)&qkv,   g_qkv);
    cudaGetSymbolAddress((void**)&actb,  g_actb);
    cudaGetSymbolAddress((void**)&acts,  g_acts);
    cudaGetSymbolAddress((void**)&hidb,  g_hidb);
    cudaGetSymbolAddress((void**)&hids,  g_hids);
    cudaGetSymbolAddress((void**)&wqb,   g_wqb);
    cudaGetSymbolAddress((void**)&wqs,   g_wqs);
    cudaGetSymbolAddress((void**)&wpb,   g_wpb);
    cudaGetSymbolAddress((void**)&wps,   g_wps);
    cudaGetSymbolAddress((void**)&w1b,   g_w1b);
    cudaGetSymbolAddress((void**)&w1s,   g_w1s);
    cudaGetSymbolAddress((void**)&w2b,   g_w2b);
    cudaGetSymbolAddress((void**)&w2s,   g_w2s);

    const int SM128 = NSTAGE * (128 + 128) * 2 * 80;  // 122880
    const int SM64  = NSTAGE * (128 + 64)  * 2 * 80;  // 92160
    cudaFuncSetAttribute(k_gemm_bf3<128, 0>, cudaFuncAttributeMaxDynamicSharedMemorySize, SM128);
    cudaFuncSetAttribute(k_gemm_bf3<128, 1>, cudaFuncAttributeMaxDynamicSharedMemorySize, SM128);
    cudaFuncSetAttribute(k_gemm_bf3<64, 2>,  cudaFuncAttributeMaxDynamicSharedMemorySize, SM64);

    const int MT = M_PAD / 128;  // 10

    // weight pre-split (deterministic, every launch)
    k_split<<<(QWN / 4 + 255) / 256, 256>>>((const float4*)qkv_w,  wqb, wqs, QWN / 4);
    k_split<<<(PWN / 4 + 255) / 256, 256>>>((const float4*)proj_w, wpb, wps, PWN / 4);
    k_split<<<(F1N / 4 + 255) / 256, 256>>>((const float4*)fc1_w,  w1b, w1s, F1N / 4);
    k_split<<<(F2N / 4 + 255) / 256, 256>>>((const float4*)fc2_w,  w2b, w2s, F2N / 4);

    // prologue
    k_patchify<<<BB * LL, 256>>>(x, attn_mask, yids, conv_w, conv_b, pex, ytab);
    k_select<<<BB, 256>>>(noise, attn_mask);
    k_gather<<<BB * NTOK, 256>>>(cls, pex);

    for (int l = 0; l < DEPTH; l++) {
        const float* qb  = qkv_b  + (size_t)l * 3 * DD;
        const float* pb  = proj_b + (size_t)l * DD;
        const float* l1w = ln1_w + l * DD; const float* l1b = ln1_b + l * DD;
        const float* l2w = ln2_w + l * DD; const float* l2b = ln2_b + l * DD;
        const float* f1b = fc1_b + (size_t)l * MLPD;
        const float* f2b = fc2_b + (size_t)l * DD;
        __nv_bfloat16* lwqb = wqb + (size_t)l * 3 * DD * DD;
        __nv_bfloat16* lwqs = wqs + (size_t)l * 3 * DD * DD;
        __nv_bfloat16* lwpb = wpb + (size_t)l * DD * DD;
        __nv_bfloat16* lwps = wps + (size_t)l * DD * DD;
        __nv_bfloat16* lw1b = w1b + (size_t)l * MLPD * DD;
        __nv_bfloat16* lw1s = w1s + (size_t)l * MLPD * DD;
        __nv_bfloat16* lw2b = w2b + (size_t)l * DD * MLPD;
        __nv_bfloat16* lw2s = w2s + (size_t)l * DD * MLPD;

        k_ln_sp<<<MROWS, 256>>>(carry, l1w, l1b);
        k_gemm_bf3<128, 0><<<dim3(3 * DD / 128, MT), 256, SM128>>>(
            actb, acts, lwqb, lwqs, qb, nullptr, qkv, nullptr, nullptr, 3 * DD, DD);
        k_scores<<<BB * NHD * NTOK, 128>>>();
        k_softmax_av<<<BB * NHD * NTOK, 128>>>();
        k_gemm_bf3<64, 2><<<dim3(DD / 64, MT), 256, SM64>>>(
            actb, acts, lwpb, lwps, pb, carry, carry, nullptr, nullptr, DD, DD);
        k_ln_sp<<<MROWS, 256>>>(carry, l2w, l2b);
        k_gemm_bf3<128, 1><<<dim3(MLPD / 128, MT), 256, SM128>>>(
            actb, acts, lw1b, lw1s, f1b, nullptr, nullptr, hidb, hids, MLPD, DD);
        k_gemm_bf3<64, 2><<<dim3(DD / 64, MT), 256, SM64>>>(
            hidb, hids, lw2b, lw2s, f2b, carry, carry, nullptr, nullptr, DD, MLPD);
    }

    k_ln<<<MROWS, 256>>>(carry, norm_w, norm_b, out);
}

// round 8
// speedup vs baseline: 2.3264x; 1.0276x over previous
#include <cuda_runtime.h>
#include <cuda_bf16.h>
#include <math.h>
#include <cstdint>

#define BB   16
#define HIN  12
#define WIN  2500
#define QQ   100
#define GW   25
#define LL   300
#define LEN_KEEP 75
#define NTOK 76
#define DD   768
#define DH   384
#define NHD  12
#define HD   64
#define DEPTH 12
#define MLPD 3072
#define SCALE 0.125f
#define EPS_LN 1e-5f
#define MROWS (BB * NTOK)     // 1216
#define M_PAD 1280            // 10 tiles of 128

#define QWN  (DEPTH * 3 * DD * DD)
#define PWN  (DEPTH * DD * DD)
#define F1N  (DEPTH * MLPD * DD)
#define F2N  (DEPTH * DD * MLPD)

// ---------------- scratch (device globals; no allocation allowed) -----------
__device__ float g_hfull[BB * LL * DD];
__device__ float g_carry[M_PAD * DD];
__device__ float g_qkv[M_PAD * 3 * DD];
__device__ float g_att[BB * NHD * NTOK * NTOK];
__device__ int   g_idsk[BB * LEN_KEEP];
__device__ float g_m[BB * NTOK];
__device__ unsigned g_gmax;

// split activations (big/small bf16)
__device__ __nv_bfloat16 g_actb[M_PAD * DD],   g_acts[M_PAD * DD];
__device__ __nv_bfloat16 g_hidb[M_PAD * MLPD], g_hids[M_PAD * MLPD];
// split weights
__device__ __nv_bfloat16 g_wqb[QWN], g_wqs[QWN];
__device__ __nv_bfloat16 g_wpb[PWN], g_wps[PWN];
__device__ __nv_bfloat16 g_w1b[F1N], g_w1s[F1N];
__device__ __nv_bfloat16 g_w2b[F2N], g_w2s[F2N];

// monotone float<->uint encoding for atomicMax on floats
__device__ __forceinline__ unsigned fenc(float f) {
    unsigned u = __float_as_uint(f);
    return (u & 0x80000000u) ? ~u : (u | 0x80000000u);
}
__device__ __forceinline__ float fdec(unsigned u) {
    return (u & 0x80000000u) ? __uint_as_float(u & 0x7fffffffu) : __uint_as_float(~u);
}

// ---------------- asm helpers -------------------------------------------------
#define CP_ASYNC16(dst, src) \
    asm volatile("cp.async.cg.shared.global [%0], [%1], 16;" :: "r"(dst), "l"(src))
#define CP_COMMIT() asm volatile("cp.async.commit_group;" ::: "memory")
#define LDSM4(r0, r1, r2, r3, addr)                                          \
    asm volatile("ldmatrix.sync.aligned.m8n8.x4.shared.b16 {%0,%1,%2,%3}, [%4];" \
        : "=r"(r0), "=r"(r1), "=r"(r2), "=r"(r3) : "r"(addr))

__device__ __forceinline__ void mma_bf16(float* d, const uint32_t* a,
                                         uint32_t b0, uint32_t b1) {
    asm volatile(
        "mma.sync.aligned.m16n8k16.row.col.f32.bf16.bf16.f32 "
        "{%0,%1,%2,%3}, {%4,%5,%6,%7}, {%8,%9}, {%0,%1,%2,%3};"
        : "+f"(d[0]), "+f"(d[1]), "+f"(d[2]), "+f"(d[3])
        : "r"(a[0]), "r"(a[1]), "r"(a[2]), "r"(a[3]), "r"(b0), "r"(b1));
}

__device__ __forceinline__ uint32_t pack_big(float v0, float v1, float& r0, float& r1) {
    __nv_bfloat16 b0 = __float2bfloat16(v0);
    __nv_bfloat16 b1 = __float2bfloat16(v1);
    r0 = v0 - __bfloat162float(b0);
    r1 = v1 - __bfloat162float(b1);
    return (uint32_t)__bfloat16_as_ushort(b0) | ((uint32_t)__bfloat16_as_ushort(b1) << 16);
}
__device__ __forceinline__ uint32_t pack_bf2(float v0, float v1) {
    __nv_bfloat16 b0 = __float2bfloat16(v0);
    __nv_bfloat16 b1 = __float2bfloat16(v1);
    return (uint32_t)__bfloat16_as_ushort(b0) | ((uint32_t)__bfloat16_as_ushort(b1) << 16);
}

// ---------------- weight split kernel -----------------------------------------
__global__ void k_split(const float4* __restrict__ src,
                        __nv_bfloat16* __restrict__ dstb,
                        __nv_bfloat16* __restrict__ dsts, int n4) {
    int i = blockIdx.x * blockDim.x + threadIdx.x;
    if (i >= n4) return;
    float4 v = src[i];
    float s0, s1, s2, s3;
    uint32_t bw0 = pack_big(v.x, v.y, s0, s1);
    uint32_t bw1 = pack_big(v.z, v.w, s2, s3);
    uint32_t sw0 = pack_bf2(s0, s1);
    uint32_t sw1 = pack_bf2(s2, s3);
    *(uint2*)&dstb[(size_t)i * 4] = make_uint2(bw0, bw1);
    *(uint2*)&dsts[(size_t)i * 4] = make_uint2(sw0, sw1);
}

// ---------------- bf16x3 pipelined GEMM ---------------------------------------
// C = A[M,K] @ W[N,K]^T + bias (+ops). A,W pre-split bf16 (big/small).
// BM=128, BK=32, 256 threads (8 warps: 4M x 2N). Warp tile 32 x BN/2.
// smem rows padded to 80 bytes. NST-stage cp.async. 2 CTAs/SM.
// MODE 0: bias -> fp32 C ; MODE 1: bias+gelu -> split bf16 (Cb,Cs)
// MODE 2: bias+res -> fp32 C
template <int BN, int MODE, int NST>
__global__ void __launch_bounds__(256, 2)
k_gemm_bf3(const __nv_bfloat16* __restrict__ Ab_g, const __nv_bfloat16* __restrict__ As_g,
           const __nv_bfloat16* __restrict__ Wb_g, const __nv_bfloat16* __restrict__ Ws_g,
           const float* __restrict__ bias, const float* __restrict__ res,
           float* __restrict__ C, __nv_bfloat16* __restrict__ Cb,
           __nv_bfloat16* __restrict__ Cs, int Ncols, int K) {
    extern __shared__ char sh[];
    const uint32_t STAGE = (128 + BN) * 2 * 80;   // bytes per stage
    const uint32_t AOFF = 128 * 80;               // one A tile bytes
    const uint32_t WOFF = BN * 80;
    uint32_t sbase = (uint32_t)__cvta_generic_to_shared(sh);

    const int tid = threadIdx.x;
    const int wid = tid >> 5, lane = tid & 31;
    const int g = lane >> 2, t = lane & 3;
    const int lrow = lane & 7, seg = lane >> 3;
    const int warp_m = wid & 3, warp_n = wid >> 2;
    const int wm0 = warp_m * 32;
    const int wn0 = warp_n * (BN / 2);
    const int m0 = blockIdx.y * 128, n0 = blockIdx.x * BN;
    const int NI = BN / 16;
    const int NCH = (128 + BN) * 2 * 4;           // 16B chunks per stage
    const int nC = K >> 5;

    float acc[2][NI][4];
    #pragma unroll
    for (int mi = 0; mi < 2; mi++)
        #pragma unroll
        for (int ni = 0; ni < NI; ni++)
            #pragma unroll
            for (int j = 0; j < 4; j++) acc[mi][ni][j] = 0.f;

    auto load = [&](int c) {
        int k0 = c << 5;
        uint32_t base = sbase + (uint32_t)(c % NST) * STAGE;
        #pragma unroll
        for (int i = tid; i < NCH; i += 256) {
            const __nv_bfloat16* gsrc;
            uint32_t dst;
            if (i < 512) {
                int row = i >> 2, j = i & 3;
                gsrc = Ab_g + (size_t)(m0 + row) * K + k0 + j * 8;
                dst = base + row * 80 + j * 16;
            } else if (i < 1024) {
                int i2 = i - 512;
                int row = i2 >> 2, j = i2 & 3;
                gsrc = As_g + (size_t)(m0 + row) * K + k0 + j * 8;
                dst = base + AOFF + row * 80 + j * 16;
            } else if (i < 1024 + BN * 4) {
                int i2 = i - 1024;
                int row = i2 >> 2, j = i2 & 3;
                gsrc = Wb_g + (size_t)(n0 + row) * K + k0 + j * 8;
                dst = base + 2 * AOFF + row * 80 + j * 16;
            } else {
                int i2 = i - 1024 - BN * 4;
                int row = i2 >> 2, j = i2 & 3;
                gsrc = Ws_g + (size_t)(n0 + row) * K + k0 + j * 8;
                dst = base + 2 * AOFF + WOFF + row * 80 + j * 16;
            }
            CP_ASYNC16(dst, gsrc);
        }
        CP_COMMIT();
    };

    // prologue: fill NST-1 stages
    #pragma unroll
    for (int s = 0; s < NST - 1; s++) load(s);

    for (int c = 0; c < nC; c++) {
        if (c + NST - 1 < nC) load(c + NST - 1);
        else CP_COMMIT();
        asm volatile("cp.async.wait_group %0;" :: "n"(NST - 1));
        __syncthreads();

        uint32_t base = sbase + (uint32_t)(c % NST) * STAGE;
        uint32_t aB = base, aS = base + AOFF;
        uint32_t wB = base + 2 * AOFF, wS = wB + WOFF;

        #pragma unroll
        for (int ks = 0; ks < 2; ks++) {
            uint32_t ab[2][4], as_[2][4];
            #pragma unroll
            for (int mi = 0; mi < 2; mi++) {
                uint32_t off = (uint32_t)((wm0 + mi * 16 + (seg & 1) * 8 + lrow) * 80
                                          + ks * 32 + (seg >> 1) * 16);
                LDSM4(ab[mi][0], ab[mi][1], ab[mi][2], ab[mi][3], aB + off);
                LDSM4(as_[mi][0], as_[mi][1], as_[mi][2], as_[mi][3], aS + off);
            }
            uint32_t wb[NI][2], ws[NI][2];
            #pragma unroll
            for (int np = 0; np < NI / 2; np++) {
                uint32_t off = (uint32_t)((wn0 + np * 16 + (seg >> 1) * 8 + lrow) * 80
                                          + ks * 32 + (seg & 1) * 16);
                LDSM4(wb[2 * np][0], wb[2 * np][1], wb[2 * np + 1][0], wb[2 * np + 1][1], wB + off);
                LDSM4(ws[2 * np][0], ws[2 * np][1], ws[2 * np + 1][0], ws[2 * np + 1][1], wS + off);
            }
            // term-major: maximize independent MMAs between acc reuse
            #pragma unroll
            for (int ni = 0; ni < NI; ni++)
                #pragma unroll
                for (int mi = 0; mi < 2; mi++)
                    mma_bf16(acc[mi][ni], ab[mi], wb[ni][0], wb[ni][1]);
            #pragma unroll
            for (int ni = 0; ni < NI; ni++)
                #pragma unroll
                for (int mi = 0; mi < 2; mi++)
                    mma_bf16(acc[mi][ni], as_[mi], wb[ni][0], wb[ni][1]);
            #pragma unroll
            for (int ni = 0; ni < NI; ni++)
                #pragma unroll
                for (int mi = 0; mi < 2; mi++)
                    mma_bf16(acc[mi][ni], ab[mi], ws[ni][0], ws[ni][1]);
        }
        __syncthreads();
    }

    // epilogue: c0,c1 -> row g cols 2t,2t+1 ; c2,c3 -> row g+8
    #pragma unroll
    for (int mi = 0; mi < 2; mi++) {
        int r0 = m0 + wm0 + mi * 16 + g;
        int r1 = r0 + 8;
        #pragma unroll
        for (int ni = 0; ni < NI; ni++) {
            int n = n0 + wn0 + ni * 8 + 2 * t;
            float b0 = bias[n], b1 = bias[n + 1];
            float v0 = acc[mi][ni][0] + b0;
            float v1 = acc[mi][ni][1] + b1;
            float v2 = acc[mi][ni][2] + b0;
            float v3 = acc[mi][ni][3] + b1;
            if (MODE == 1) {
                v0 = 0.5f * v0 * (1.f + erff(v0 * 0.70710678118654752f));
                v1 = 0.5f * v1 * (1.f + erff(v1 * 0.70710678118654752f));
                v2 = 0.5f * v2 * (1.f + erff(v2 * 0.70710678118654752f));
                v3 = 0.5f * v3 * (1.f + erff(v3 * 0.70710678118654752f));
                float s0, s1, s2, s3;
                uint32_t bw0 = pack_big(v0, v1, s0, s1);
                uint32_t bw1 = pack_big(v2, v3, s2, s3);
                *(uint32_t*)&Cb[(size_t)r0 * Ncols + n] = bw0;
                *(uint32_t*)&Cb[(size_t)r1 * Ncols + n] = bw1;
                *(uint32_t*)&Cs[(size_t)r0 * Ncols + n] = pack_bf2(s0, s1);
                *(uint32_t*)&Cs[(size_t)r1 * Ncols + n] = pack_bf2(s2, s3);
            } else {
                if (MODE == 2) {
                    v0 += res[(size_t)r0 * Ncols + n];
                    v1 += res[(size_t)r0 * Ncols + n + 1];
                    v2 += res[(size_t)r1 * Ncols + n];
                    v3 += res[(size_t)r1 * Ncols + n + 1];
                }
                *(float2*)&C[(size_t)r0 * Ncols + n] = make_float2(v0, v1);
                *(float2*)&C[(size_t)r1 * Ncols + n] = make_float2(v2, v3);
            }
        }
    }
}

// ---------------- patchify ---------------------------------------------------
__global__ void k_patchify(const float* __restrict__ x,
                           const float* __restrict__ attn_mask,
                           const int*   __restrict__ yids,
                           const float* __restrict__ conv_w,
                           const float* __restrict__ conv_b,
                           const float* __restrict__ pex,
                           const float* __restrict__ ytab) {
    int bl = blockIdx.x;
    int b = bl / LL, l = bl % LL;
    int gh = l / GW, gw = l % GW;
    __shared__ float patch[QQ];
    const float* xrow = x + ((size_t)b * HIN + gh) * WIN + gw * QQ;
    for (int i = threadIdx.x; i < QQ; i += blockDim.x) patch[i] = xrow[i];
    __syncthreads();
    float am = attn_mask[b * LL + l];
    int yid = yids[b * LL + l];
    for (int d = threadIdx.x; d < DD; d += blockDim.x) {
        const float* w = conv_w + d * QQ;
        float acc = 0.f;
        #pragma unroll 4
        for (int q = 0; q < QQ; q++) acc += patch[q] * w[q];
        acc += conv_b[d];
        if (d < DH) acc += ytab[yid * DH + d];
        else        acc += am * pex[(gw + 1) * DH + (d - DH)];
        g_hfull[((size_t)b * LL + l) * DD + d] = acc;
    }
}

// ---------------- per-batch stable argsort + keep / mask build ---------------
__global__ void k_select(const float* __restrict__ noise,
                         const float* __restrict__ attn_mask) {
    int b = blockIdx.x;
    __shared__ float ns[LL];
    __shared__ int ids[LL];
    __shared__ unsigned char keep[LL];
    for (int i = threadIdx.x; i < LL; i += blockDim.x) { ns[i] = noise[b * LL + i]; keep[i] = 0; }
    __syncthreads();
    for (int i = threadIdx.x; i < LL; i += blockDim.x) {
        float vi = ns[i];
        int r = 0;
        for (int j = 0; j < LL; j++) {
            float vj = ns[j];
            r += (vj < vi) || (vj == vi && j < i);
        }
        ids[r] = i;
    }
    __syncthreads();
    for (int t = threadIdx.x; t < LEN_KEEP; t += blockDim.x) {
        g_idsk[b * LEN_KEEP + t] = ids[t];
        keep[ids[t]] = 1;
    }
    __syncthreads();
    for (int i = threadIdx.x; i < LL; i += blockDim.x) {
        if (keep[i]) {
            int pos = 0;
            for (int j = 0; j < i; j++) pos += keep[j];
            g_m[b * NTOK + 1 + pos] = attn_mask[b * LL + i];
        }
    }
    if (threadIdx.x == 0) g_m[b * NTOK] = 1.f;
}

// ---------------- gather kept tokens, prepend cls ----------------------------
__global__ void k_gather(const float* __restrict__ cls_token,
                         const float* __restrict__ pex) {
    int bt = blockIdx.x;
    int b = bt / NTOK, t = bt % NTOK;
    float* outp = g_carry + (size_t)bt * DD;
    if (t == 0) {
        for (int d = threadIdx.x; d < DD; d += blockDim.x)
            outp[d] = cls_token[d] + (d >= DH ? pex[d - DH] : 0.f);
    } else {
        int l = g_idsk[b * LEN_KEEP + (t - 1)];
        const float* src = g_hfull + ((size_t)b * LL + l) * DD;
        for (int d = threadIdx.x; d < DD; d += blockDim.x) outp[d] = src[d];
    }
}

// ---------------- layernorm (fp32 out, final) ---------------------------------
__global__ void k_ln(const float* __restrict__ in,
                     const float* __restrict__ w,
                     const float* __restrict__ bias,
                     float* __restrict__ out) {
    int r = blockIdx.x;
    const float* p = in + (size_t)r * DD;
    __shared__ float red[256];
    float s = 0.f;
    for (int d = threadIdx.x; d < DD; d += 256) s += p[d];
    red[threadIdx.x] = s; __syncthreads();
    for (int o = 128; o > 0; o >>= 1) {
        if (threadIdx.x < o) red[threadIdx.x] += red[threadIdx.x + o];
        __syncthreads();
    }
    float mu = red[0] * (1.f / DD);
    __syncthreads();
    float v = 0.f;
    for (int d = threadIdx.x; d < DD; d += 256) { float t = p[d] - mu; v += t * t; }
    red[threadIdx.x] = v; __syncthreads();
    for (int o = 128; o > 0; o >>= 1) {
        if (threadIdx.x < o) red[threadIdx.x] += red[threadIdx.x + o];
        __syncthreads();
    }
    float rstd = rsqrtf(red[0] * (1.f / DD) + EPS_LN);
    for (int d = threadIdx.x; d < DD; d += 256)
        out[(size_t)r * DD + d] = (p[d] - mu) * rstd * w[d] + bias[d];
}

// ---------------- layernorm (split bf16 out; also resets g_gmax) --------------
__global__ void k_ln_sp(const float* __restrict__ in,
                        const float* __restrict__ w,
                        const float* __restrict__ bias) {
    int r = blockIdx.x;
    if (r == 0 && threadIdx.x == 0) g_gmax = 0u;
    const float* p = in + (size_t)r * DD;
    __shared__ float red[256];
    float s = 0.f;
    for (int d = threadIdx.x; d < DD; d += 256) s += p[d];
    red[threadIdx.x] = s; __syncthreads();
    for (int o = 128; o > 0; o >>= 1) {
        if (threadIdx.x < o) red[threadIdx.x] += red[threadIdx.x + o];
        __syncthreads();
    }
    float mu = red[0] * (1.f / DD);
    __syncthreads();
    float v = 0.f;
    for (int d = threadIdx.x; d < DD; d += 256) { float t = p[d] - mu; v += t * t; }
    red[threadIdx.x] = v; __syncthreads();
    for (int o = 128; o > 0; o >>= 1) {
        if (threadIdx.x < o) red[threadIdx.x] += red[threadIdx.x + o];
        __syncthreads();
    }
    float rstd = rsqrtf(red[0] * (1.f / DD) + EPS_LN);
    for (int d = threadIdx.x; d < DD; d += 256) {
        float val = (p[d] - mu) * rstd * w[d] + bias[d];
        __nv_bfloat16 big = __float2bfloat16(val);
        g_actb[(size_t)r * DD + d] = big;
        g_acts[(size_t)r * DD + d] = __float2bfloat16(val - __bfloat162float(big));
    }
}

// ---------------- attention: scores + global max -----------------------------
__global__ void k_scores() {
    int idx = blockIdx.x;
    int n = idx % NTOK;
    int bh = idx / NTOK;
    int h = bh % NHD, b = bh / NHD;
    __shared__ float qsh[HD];
    __shared__ float red[128];
    const float* qp = g_qkv + (size_t)(b * NTOK + n) * (3 * DD) + h * HD;
    if (threadIdx.x < HD) qsh[threadIdx.x] = qp[threadIdx.x];
    __syncthreads();
    float mn = g_m[b * NTOK + n];
    float lmax = -3.4e38f;
    int m = threadIdx.x;
    if (m < NTOK) {
        const float* kp = g_qkv + (size_t)(b * NTOK + m) * (3 * DD) + DD + h * HD;
        float dot = 0.f;
        #pragma unroll
        for (int d = 0; d < HD; d++) dot += qsh[d] * kp[d];
        float logit = dot * SCALE;
        float mm = mn * g_m[b * NTOK + m];
        if (mm == 0.f) logit = -INFINITY; else lmax = logit;
        g_att[(size_t)idx * NTOK + m] = logit;
    }
    red[threadIdx.x] = lmax; __syncthreads();
    for (int o = 64; o > 0; o >>= 1) {
        if (threadIdx.x < o) red[threadIdx.x] = fmaxf(red[threadIdx.x], red[threadIdx.x + o]);
        __syncthreads();
    }
    if (threadIdx.x == 0 && red[0] > -3.3e38f) atomicMax(&g_gmax, fenc(red[0]));
}

// ---------------- softmax (global-max variant) + AV -> split bf16 -------------
__global__ void k_softmax_av() {
    int idx = blockIdx.x;
    int n = idx % NTOK;
    int bh = idx / NTOK;
    int h = bh % NHD, b = bh / NHD;
    __shared__ float p[NTOK];
    __shared__ float red[128];
    float g = fdec(g_gmax);
    float e = 0.f;
    if (threadIdx.x < NTOK) {
        e = expf(g_att[(size_t)idx * NTOK + threadIdx.x] - g);
        p[threadIdx.x] = e;
    }
    red[threadIdx.x] = e; __syncthreads();
    for (int o = 64; o > 0; o >>= 1) {
        if (threadIdx.x < o) red[threadIdx.x] += red[threadIdx.x + o];
        __syncthreads();
    }
    float inv = 1.f / (red[0] + 1e-9f);
    if (threadIdx.x < HD) {
        const float* vp = g_qkv + (size_t)(b * NTOK) * (3 * DD) + 2 * DD + h * HD + threadIdx.x;
        float acc = 0.f;
        for (int m2 = 0; m2 < NTOK; m2++) acc += p[m2] * vp[(size_t)m2 * 3 * DD];
        float val = acc * inv;
        __nv_bfloat16 big = __float2bfloat16(val);
        size_t o2 = (size_t)(b * NTOK + n) * DD + h * HD + threadIdx.x;
        g_actb[o2] = big;
        g_acts[o2] = __float2bfloat16(val - __bfloat162float(big));
    }
}

// ---------------- launch -----------------------------------------------------
extern "C" void kernel_launch(void* const* d_in, const int* in_sizes, int n_in,
                              void* d_out, int out_size) {
    const float* x         = (const float*)d_in[0];
    const float* attn_mask = (const float*)d_in[1];
    const int*   yids      = (const int*)  d_in[2];
    const float* noise     = (const float*)d_in[3];
    const float* conv_w    = (const float*)d_in[4];
    const float* conv_b    = (const float*)d_in[5];
    const float* pex       = (const float*)d_in[6];
    const float* ytab      = (const float*)d_in[7];
    const float* cls       = (const float*)d_in[8];
    const float* qkv_w     = (const float*)d_in[9];
    const float* qkv_b     = (const float*)d_in[10];
    const float* proj_w    = (const float*)d_in[11];
    const float* proj_b    = (const float*)d_in[12];
    const float* ln1_w     = (const float*)d_in[13];
    const float* ln1_b     = (const float*)d_in[14];
    const float* ln2_w     = (const float*)d_in[15];
    const float* ln2_b     = (const float*)d_in[16];
    const float* fc1_w     = (const float*)d_in[17];
    const float* fc1_b     = (const float*)d_in[18];
    const float* fc2_w     = (const float*)d_in[19];
    const float* fc2_b     = (const float*)d_in[20];
    const float* norm_w    = (const float*)d_in[21];
    const float* norm_b    = (const float*)d_in[22];
    float* out = (float*)d_out;

    float *carry, *qkv;
    __nv_bfloat16 *actb, *acts, *hidb, *hids;
    __nv_bfloat16 *wqb, *wqs, *wpb, *wps, *w1b, *w1s, *w2b, *w2s;
    cudaGetSymbolAddress((void**)&carry, g_carry);
    cudaGetSymbolAddress((void**)&qkv,   g_qkv);
    cudaGetSymbolAddress((void**)&actb,  g_actb);
    cudaGetSymbolAddress((void**)&acts,  g_acts);
    cudaGetSymbolAddress((void**)&hidb,  g_hidb);
    cudaGetSymbolAddress((void**)&hids,  g_hids);
    cudaGetSymbolAddress((void**)&wqb,   g_wqb);
    cudaGetSymbolAddress((void**)&wqs,   g_wqs);
    cudaGetSymbolAddress((void**)&wpb,   g_wpb);
    cudaGetSymbolAddress((void**)&wps,   g_wps);
    cudaGetSymbolAddress((void**)&w1b,   g_w1b);
    cudaGetSymbolAddress((void**)&w1s,   g_w1s);
    cudaGetSymbolAddress((void**)&w2b,   g_w2b);
    cudaGetSymbolAddress((void**)&w2s,   g_w2s);

    const int SM128 = 2 * (128 + 128) * 2 * 80;  // 81920 (NST=2) -> 2 CTAs/SM
    const int SM64  = 3 * (128 + 64)  * 2 * 80;  // 92160 (NST=3) -> 2 CTAs/SM
    cudaFuncSetAttribute(k_gemm_bf3<128, 0, 2>, cudaFuncAttributeMaxDynamicSharedMemorySize, SM128);
    cudaFuncSetAttribute(k_gemm_bf3<128, 1, 2>, cudaFuncAttributeMaxDynamicSharedMemorySize, SM128);
    cudaFuncSetAttribute(k_gemm_bf3<64, 2, 3>,  cudaFuncAttributeMaxDynamicSharedMemorySize, SM64);

    const int MT = M_PAD / 128;  // 10

    // weight pre-split (deterministic, every launch)
    k_split<<<(QWN / 4 + 255) / 256, 256>>>((const float4*)qkv_w,  wqb, wqs, QWN / 4);
    k_split<<<(PWN / 4 + 255) / 256, 256>>>((const float4*)proj_w, wpb, wps, PWN / 4);
    k_split<<<(F1N / 4 + 255) / 256, 256>>>((const float4*)fc1_w,  w1b, w1s, F1N / 4);
    k_split<<<(F2N / 4 + 255) / 256, 256>>>((const float4*)fc2_w,  w2b, w2s, F2N / 4);

    // prologue
    k_patchify<<<BB * LL, 256>>>(x, attn_mask, yids, conv_w, conv_b, pex, ytab);
    k_select<<<BB, 256>>>(noise, attn_mask);
    k_gather<<<BB * NTOK, 256>>>(cls, pex);

    for (int l = 0; l < DEPTH; l++) {
        const float* qb  = qkv_b  + (size_t)l * 3 * DD;
        const float* pb  = proj_b + (size_t)l * DD;
        const float* l1w = ln1_w + l * DD; const float* l1b = ln1_b + l * DD;
        const float* l2w = ln2_w + l * DD; const float* l2b = ln2_b + l * DD;
        const float* f1b = fc1_b + (size_t)l * MLPD;
        const float* f2b = fc2_b + (size_t)l * DD;
        __nv_bfloat16* lwqb = wqb + (size_t)l * 3 * DD * DD;
        __nv_bfloat16* lwqs = wqs + (size_t)l * 3 * DD * DD;
        __nv_bfloat16* lwpb = wpb + (size_t)l * DD * DD;
        __nv_bfloat16* lwps = wps + (size_t)l * DD * DD;
        __nv_bfloat16* lw1b = w1b + (size_t)l * MLPD * DD;
        __nv_bfloat16* lw1s = w1s + (size_t)l * MLPD * DD;
        __nv_bfloat16* lw2b = w2b + (size_t)l * DD * MLPD;
        __nv_bfloat16* lw2s = w2s + (size_t)l * DD * MLPD;

        k_ln_sp<<<MROWS, 256>>>(carry, l1w, l1b);
        k_gemm_bf3<128, 0, 2><<<dim3(3 * DD / 128, MT), 256, SM128>>>(
            actb, acts, lwqb, lwqs, qb, nullptr, qkv, nullptr, nullptr, 3 * DD, DD);
        k_scores<<<BB * NHD * NTOK, 128>>>();
        k_softmax_av<<<BB * NHD * NTOK, 128>>>();
        k_gemm_bf3<64, 2, 3><<<dim3(DD / 64, MT), 256, SM64>>>(
            actb, acts, lwpb, lwps, pb, carry, carry, nullptr, nullptr, DD, DD);
        k_ln_sp<<<MROWS, 256>>>(carry, l2w, l2b);
        k_gemm_bf3<128, 1, 2><<<dim3(MLPD / 128, MT), 256, SM128>>>(
            actb, acts, lw1b, lw1s, f1b, nullptr, nullptr, hidb, hids, MLPD, DD);
        k_gemm_bf3<64, 2, 3><<<dim3(DD / 64, MT), 256, SM64>>>(
            hidb, hids, lw2b, lw2s, f2b, carry, carry, nullptr, nullptr, DD, MLPD);
    }

    k_ln<<<MROWS, 256>>>(carry, norm_w, norm_b, out);
}